// round 11
// baseline (speedup 1.0000x reference)
#include <cuda_runtime.h>
#include <cuda_bf16.h>
#include <math.h>

// ---------------- problem constants ----------------
#define TSZ    480000
#define BATCH  8
#define CHUNK  4096
#define STRIDE 3072
#define NCH    157
#define NF     13
#define NFFT   1024
#define HOP    256
#define FBINS  513
#define HDIM   256
#define EDIM   128
#define N3H    768
#define SEQ    (BATCH*NCH)   // 1256
#define ROWS   (SEQ*NF)      // 16328
#define CPB    (NCH*NF)      // 2041
#define KPAD   528
#define PWLD   1152
#define NGB    1026
#define PI_F   3.14159265358979323846f

// ---------------- scratch ----------------
__device__ __nv_bfloat16 g_magh[ROWS*KPAD], g_magl[ROWS*KPAD];
__device__ float g_cosp[ROWS*FBINS];
__device__ float g_sinp[ROWS*FBINS];
__device__ float g_xg  [ROWS*N3H];
__device__ __nv_bfloat16 g_hsh[ROWS*HDIM], g_hsl[ROWS*HDIM];
__device__ float g_gb  [ROWS*NGB];
__device__ float g_y   [ROWS*NFFT];
__device__ float g_embrow[BATCH*N3H];
__device__ float g_wsum[CHUNK];
__device__ __nv_bfloat16 g_wxh[N3H*KPAD], g_wxl[N3H*KPAD];   // [n][k]
__device__ __nv_bfloat16 g_pwh[PWLD*HDIM], g_pwl[PWLD*HDIM]; // [n][k]
__device__ __nv_bfloat16 g_whh[N3H*HDIM], g_whl[N3H*HDIM];   // [n][k], n gate-natural
__device__ float g_twr[512], g_twi[512];
__device__ float g_win[NFFT];

__device__ __forceinline__ float sigf(float x) { return 1.f/(1.f + expf(-x)); }
__device__ __forceinline__ float sigf_fast(float x) { return 1.f/(1.f + __expf(-x)); }
__device__ __forceinline__ float tanh_fast(float x) { return 2.f/(1.f + __expf(-2.f*x)) - 1.f; }

__device__ __forceinline__ void bsplit(float v, __nv_bfloat16& h, __nv_bfloat16& l) {
    h = __float2bfloat16(v);
    l = __float2bfloat16(v - __bfloat162float(h));
}

__device__ __forceinline__ void mmab(float* c, const unsigned* a, unsigned b0, unsigned b1) {
    asm volatile("mma.sync.aligned.m16n8k16.row.col.f32.bf16.bf16.f32 "
        "{%0,%1,%2,%3}, {%4,%5,%6,%7}, {%8,%9}, {%0,%1,%2,%3};"
        : "+f"(c[0]), "+f"(c[1]), "+f"(c[2]), "+f"(c[3])
        : "r"(a[0]), "r"(a[1]), "r"(a[2]), "r"(a[3]), "r"(b0), "r"(b1));
}
__device__ __forceinline__ void cpa16(unsigned d, const void* s, int sz) {
    asm volatile("cp.async.ca.shared.global [%0], [%1], 16, %2;" :: "r"(d), "l"(s), "r"(sz));
}
#define CPA_COMMIT() asm volatile("cp.async.commit_group;")
#define CPA_WAIT()   asm volatile("cp.async.wait_all;" ::: "memory")

// ---------------- merged prep ----------------
#define PB_TAB 16
#define PB_WX  1584   // N3H*KPAD/256
#define PB_PW  1152   // PWLD*HDIM/256
#define PB_WH  768    // N3H*HDIM/256
__global__ void k_prep(const float* __restrict__ wx,
                       const float* __restrict__ pw,
                       const float* __restrict__ wh,
                       const float* __restrict__ emb_table,
                       const int*   __restrict__ effect_id) {
    __shared__ float se[EDIM];
    const int bx = blockIdx.x, tid = threadIdx.x;
    if (bx < PB_TAB) {
        int i = bx*256 + tid;
        if (i < 512) {
            float s, c; sincosf(-(2.f*PI_F/NFFT)*i, &s, &c);
            g_twr[i] = c; g_twi[i] = s;
        }
        if (i < NFFT)
            g_win[i] = 0.5f - 0.5f*cosf((2.f*PI_F/NFFT)*i);
        if (i < CHUNK) {
            float ws = 0.f;
            for (int fi = 0; fi < NF; fi++) {
                int d = i - fi*HOP;
                if (d >= 0 && d < NFFT) {
                    float w = 0.5f - 0.5f*cosf((2.f*PI_F/NFFT)*d);
                    ws += w*w;
                }
            }
            g_wsum[i] = ws;
        }
    } else if (bx < PB_TAB + PB_WX) {
        int i = (bx - PB_TAB)*256 + tid;
        int n = i / KPAD, k = i % KPAD;
        float v = (k < FBINS) ? wx[(size_t)k*N3H + n] : 0.f;
        bsplit(v, g_wxh[i], g_wxl[i]);
    } else if (bx < PB_TAB + PB_WX + PB_PW) {
        int j = (bx - PB_TAB - PB_WX)*256 + tid;
        int n = j / HDIM, k = j % HDIM;
        float v = (n < NGB) ? pw[(size_t)k*NGB + n] : 0.f;
        bsplit(v, g_pwh[j], g_pwl[j]);
    } else if (bx < PB_TAB + PB_WX + PB_PW + PB_WH) {
        int j = (bx - PB_TAB - PB_WX - PB_PW)*256 + tid;
        int n = j >> 8, k = j & 255;
        float v = wh[(size_t)k*N3H + n];
        bsplit(v, g_whh[j], g_whl[j]);
    } else {
        int b = bx - PB_TAB - PB_WX - PB_PW - PB_WH;   // 0..7
        if (tid < EDIM) se[tid] = emb_table[effect_id[b]*EDIM + tid];
        __syncthreads();
        for (int j = tid; j < N3H; j += 256) {
            float acc = 0.f;
            #pragma unroll 8
            for (int k = 0; k < EDIM; k++)
                acc += se[k] * wx[(size_t)(FBINS + k)*N3H + j];
            g_embrow[b*N3H + j] = acc;
        }
    }
}

// ---------------- forward STFT: 2 real frames per complex FFT, radix-4 core ----------------
__global__ void k_fwdfft(const float* __restrict__ audio) {
    __shared__ float sr[NFFT], si[NFFT];
    __shared__ float twr[512], twi[512];
    const int pr  = blockIdx.x;
    const int tid = threadIdx.x;
    const int fr0 = 2*pr, fr1 = fr0 + 1;
    const int b0 = fr0 / CPB, r0 = fr0 % CPB;
    const int b1 = fr1 / CPB, r1 = fr1 % CPB;
    const int base0 = (r0/NF)*STRIDE + (r0%NF)*HOP;
    const int base1 = (r1/NF)*STRIDE + (r1%NF)*HOP;

    for (int k = tid; k < 512; k += 256) { twr[k] = g_twr[k]; twi[k] = g_twi[k]; }
    for (int n = tid; n < NFFT; n += 256) {
        int s0 = base0 + n, s1 = base1 + n;
        float v0 = (s0 < TSZ) ? audio[b0*TSZ + s0] : 0.f;
        float v1 = (s1 < TSZ) ? audio[b1*TSZ + s1] : 0.f;
        float w = g_win[n];
        int j = __brev((unsigned)n) >> 22;
        sr[j] = v0*w; si[j] = v1*w;
    }
    __syncthreads();
    #pragma unroll
    for (int s = 1; s <= 9; s += 2) {
        const int h = 1 << (s-1);
        const int pos = tid & (h-1);
        const int grl = tid >> (s-1);
        const int base = (grl << (s+1)) + pos;
        const float wr1 = twr[pos << (10-s)], wi1 = twi[pos << (10-s)];
        const float wr2 = twr[pos << (9-s)],  wi2 = twi[pos << (9-s)];
        const int e3 = (pos + h) << (9-s);
        const float wr3 = twr[e3], wi3 = twi[e3];
        float x0r = sr[base],       x0i = si[base];
        float x1r = sr[base+h],     x1i = si[base+h];
        float x2r = sr[base+2*h],   x2i = si[base+2*h];
        float x3r = sr[base+3*h],   x3i = si[base+3*h];
        float t1r = wr1*x1r - wi1*x1i, t1i = wr1*x1i + wi1*x1r;
        float u0r = x0r + t1r, u0i = x0i + t1i;
        float u1r = x0r - t1r, u1i = x0i - t1i;
        float t3r = wr1*x3r - wi1*x3i, t3i = wr1*x3i + wi1*x3r;
        float u2r = x2r + t3r, u2i = x2i + t3i;
        float u3r = x2r - t3r, u3i = x2i - t3i;
        float v2r = wr2*u2r - wi2*u2i, v2i = wr2*u2i + wi2*u2r;
        float v3r = wr3*u3r - wi3*u3i, v3i = wr3*u3i + wi3*u3r;
        sr[base]       = u0r + v2r; si[base]       = u0i + v2i;
        sr[base+2*h]   = u0r - v2r; si[base+2*h]   = u0i - v2i;
        sr[base+h]     = u1r + v3r; si[base+h]     = u1i + v3i;
        sr[base+3*h]   = u1r - v3r; si[base+3*h]   = u1i - v3i;
        __syncthreads();
    }
    for (int k = tid; k < KPAD; k += 256) {
        if (k < FBINS) {
            int m = (NFFT - k) & (NFFT-1);
            float rek = sr[k], imk = si[k];
            float rem = sr[m], imm = si[m];
            float re0 = 0.5f*(rek + rem), i0 = 0.5f*(imk - imm);
            float re1 = 0.5f*(imk + imm), i1 = 0.5f*(rem - rek);
            float mag0 = sqrtf(re0*re0 + i0*i0);
            float c0, s0;
            if (mag0 > 1e-30f) { float inv = 1.f/mag0; c0 = re0*inv; s0 = i0*inv; }
            else               { c0 = 1.f; s0 = 0.f; }
            float mag1 = sqrtf(re1*re1 + i1*i1);
            float c1, s1;
            if (mag1 > 1e-30f) { float inv = 1.f/mag1; c1 = re1*inv; s1 = i1*inv; }
            else               { c1 = 1.f; s1 = 0.f; }
            bsplit(mag0, g_magh[fr0*KPAD + k], g_magl[fr0*KPAD + k]);
            bsplit(mag1, g_magh[fr1*KPAD + k], g_magl[fr1*KPAD + k]);
            g_cosp[fr0*FBINS + k] = c0; g_sinp[fr0*FBINS + k] = s0;
            g_cosp[fr1*FBINS + k] = c1; g_sinp[fr1*FBINS + k] = s1;
        } else {
            __nv_bfloat16 z = __float2bfloat16(0.f);
            g_magh[fr0*KPAD + k] = z; g_magl[fr0*KPAD + k] = z;
            g_magh[fr1*KPAD + k] = z; g_magl[fr1*KPAD + k] = z;
        }
    }
}

// ================= bf16-split 3-pass tensor GEMM (validated) =================
#define SM_PLANE (128*12)
#define SM_AH(p,r,c) smem_u[((p)*128 + (r))*12 + (c)]
#define SM_AL(p,r,c) smem_u[SM_PLANE*2 + ((p)*128 + (r))*12 + (c)]
#define SM_BH(p,r,c) smem_u[SM_PLANE*4 + ((p)*128 + (r))*12 + (c)]
#define SM_BL(p,r,c) smem_u[SM_PLANE*6 + ((p)*128 + (r))*12 + (c)]
#define SMEM_GEMM_BYTES (SM_PLANE*8*4)   // 49152

template<int NIT, int KSTRIDE>
__device__ __forceinline__ void gemm_core(
    unsigned* smem_u,
    const __nv_bfloat16* Ah_g, const __nv_bfloat16* Al_g, int a_row_max,
    const __nv_bfloat16* Bh_g, const __nv_bfloat16* Bl_g,
    int m0, int n0, float acc[2][8][4])
{
    const int tid = threadIdx.x;
    const int lane = tid & 31, wid = tid >> 5;
    const int wm = wid >> 1, wn = wid & 1;
    const int grp = lane >> 2, tig = lane & 3;
    const int row = tid >> 1, half = tid & 1;
    const int arow = m0 + row;
    const int asz = (arow < a_row_max) ? 16 : 0;
    const int brow = n0 + row;

    unsigned sbase = (unsigned)__cvta_generic_to_shared(smem_u);
    unsigned off = (row*12 + half*4)*4;
    unsigned dAh = sbase + off;
    unsigned dAl = sbase + SM_PLANE*2*4 + off;
    unsigned dBh = sbase + SM_PLANE*4*4 + off;
    unsigned dBl = sbase + SM_PLANE*6*4 + off;
    const unsigned bufB = 128*12*4;

    cpa16(dAh, Ah_g + (size_t)arow*KSTRIDE + half*8, asz);
    cpa16(dAl, Al_g + (size_t)arow*KSTRIDE + half*8, asz);
    cpa16(dBh, Bh_g + (size_t)brow*KSTRIDE + half*8, 16);
    cpa16(dBl, Bl_g + (size_t)brow*KSTRIDE + half*8, 16);
    CPA_COMMIT();
    CPA_WAIT();
    __syncthreads();

    #pragma unroll 1
    for (int it = 0; it < NIT; it++) {
        int p = it & 1, q = p ^ 1;
        if (it + 1 < NIT) {
            int k0 = (it+1)*16;
            cpa16(dAh + q*bufB, Ah_g + (size_t)arow*KSTRIDE + k0 + half*8, asz);
            cpa16(dAl + q*bufB, Al_g + (size_t)arow*KSTRIDE + k0 + half*8, asz);
            cpa16(dBh + q*bufB, Bh_g + (size_t)brow*KSTRIDE + k0 + half*8, 16);
            cpa16(dBl + q*bufB, Bl_g + (size_t)brow*KSTRIDE + k0 + half*8, 16);
            CPA_COMMIT();
        }
        unsigned afh[2][4], afl[2][4];
        #pragma unroll
        for (int mt = 0; mt < 2; mt++) {
            int rA = wm*32 + mt*16 + grp;
            afh[mt][0] = SM_AH(p, rA,   tig);
            afh[mt][1] = SM_AH(p, rA+8, tig);
            afh[mt][2] = SM_AH(p, rA,   tig+4);
            afh[mt][3] = SM_AH(p, rA+8, tig+4);
            afl[mt][0] = SM_AL(p, rA,   tig);
            afl[mt][1] = SM_AL(p, rA+8, tig);
            afl[mt][2] = SM_AL(p, rA,   tig+4);
            afl[mt][3] = SM_AL(p, rA+8, tig+4);
        }
        #pragma unroll
        for (int nt = 0; nt < 8; nt++) {
            int cB = wn*64 + nt*8 + grp;
            unsigned bh0 = SM_BH(p, cB, tig);
            unsigned bh1 = SM_BH(p, cB, tig+4);
            unsigned bl0 = SM_BL(p, cB, tig);
            unsigned bl1 = SM_BL(p, cB, tig+4);
            #pragma unroll
            for (int mt = 0; mt < 2; mt++) {
                mmab(acc[mt][nt], afh[mt], bh0, bh1);
                mmab(acc[mt][nt], afh[mt], bl0, bl1);
                mmab(acc[mt][nt], afl[mt], bh0, bh1);
            }
        }
        if (it + 1 < NIT) CPA_WAIT();
        __syncthreads();
    }
}

// ---- k_xg ----
__global__ __launch_bounds__(256, 2) void k_xg() {
    extern __shared__ unsigned smem_u[];
    const int tid = threadIdx.x;
    const int lane = tid & 31, wid = tid >> 5;
    const int wm = wid >> 1, wn = wid & 1;
    const int grp = lane >> 2, tig = lane & 3;
    const int m0 = blockIdx.y * 128, n0 = blockIdx.x * 128;
    float acc[2][8][4] = {};
    gemm_core<33, KPAD>(smem_u, g_magh, g_magl, ROWS, g_wxh, g_wxl, m0, n0, acc);
    #pragma unroll
    for (int mt = 0; mt < 2; mt++) {
        #pragma unroll
        for (int nt = 0; nt < 8; nt++) {
            int row0 = m0 + wm*32 + mt*16 + grp;
            int col0 = n0 + wn*64 + nt*8 + 2*tig;
            if (row0 < ROWS) {
                int b = row0 / CPB;
                g_xg[(size_t)row0*N3H + col0  ] = acc[mt][nt][0] + g_embrow[b*N3H + col0  ];
                g_xg[(size_t)row0*N3H + col0+1] = acc[mt][nt][1] + g_embrow[b*N3H + col0+1];
            }
            int row1 = row0 + 8;
            if (row1 < ROWS) {
                int b = row1 / CPB;
                g_xg[(size_t)row1*N3H + col0  ] = acc[mt][nt][2] + g_embrow[b*N3H + col0  ];
                g_xg[(size_t)row1*N3H + col0+1] = acc[mt][nt][3] + g_embrow[b*N3H + col0+1];
            }
        }
    }
}

// ---- k_proj ----
__global__ __launch_bounds__(256, 2) void k_proj(const float* __restrict__ pb) {
    extern __shared__ unsigned smem_u[];
    const int tid = threadIdx.x;
    const int lane = tid & 31, wid = tid >> 5;
    const int wm = wid >> 1, wn = wid & 1;
    const int grp = lane >> 2, tig = lane & 3;
    const int m0 = blockIdx.y * 128, n0 = blockIdx.x * 128;
    float acc[2][8][4] = {};
    gemm_core<16, HDIM>(smem_u, g_hsh, g_hsl, ROWS, g_pwh, g_pwl, m0, n0, acc);
    #pragma unroll
    for (int mt = 0; mt < 2; mt++) {
        #pragma unroll
        for (int nt = 0; nt < 8; nt++) {
            int row0 = m0 + wm*32 + mt*16 + grp;
            int col0 = n0 + wn*64 + nt*8 + 2*tig;
            if (row0 < ROWS) {
                if (col0   < NGB) g_gb[(size_t)row0*NGB + col0  ] = acc[mt][nt][0] + pb[col0  ];
                if (col0+1 < NGB) g_gb[(size_t)row0*NGB + col0+1] = acc[mt][nt][1] + pb[col0+1];
            }
            int row1 = row0 + 8;
            if (row1 < ROWS) {
                if (col0   < NGB) g_gb[(size_t)row1*NGB + col0  ] = acc[mt][nt][2] + pb[col0  ];
                if (col0+1 < NGB) g_gb[(size_t)row1*NGB + col0+1] = acc[mt][nt][3] + pb[col0+1];
            }
        }
    }
}

// ================= per-step tensor-core GRU (64 seqs x 192 cols, BK=32) =================
// grid (4, 20) = 80 blocks. smem (uints):
//   AH [2buf][2kg][64row][12] @0 (3072), AL @3072,
//   BH [2buf][2kg][192row][12] @6144 (9216), BL @15360. Total 24576 u = 98304 B.
// hg staging floats [64][196] aliases BH+BL region after final sync.
#define GR_AL 3072
#define GR_BH 6144
#define GR_BL 15360
#define GRUS_SMEM_BYTES (24576*4)   // 98304

__device__ __forceinline__ void grus_load(unsigned sbase, int p, int kc,
                                          int sq0, int g, int t) {
    const int tid = threadIdx.x;
    #pragma unroll
    for (int v = 0; v < 8; v++) {
        int slot = tid + v*256;               // 0..2047
        if (slot < 1536) {                    // B: weights
            int plane = slot >= 768;
            int rem = plane ? slot - 768 : slot;
            int kg = rem >= 384;
            int r2 = kg ? rem - 384 : rem;
            int br = r2 >> 1, half = r2 & 1;
            int n = ((br >> 6) << 8) + g*64 + (br & 63);   // gate-natural row
            const __nv_bfloat16* src = (plane ? g_whl : g_whh)
                                       + (size_t)n*HDIM + kc*32 + kg*16 + half*8;
            unsigned dst = sbase + (unsigned)((plane ? GR_BL : GR_BH)
                                              + ((p*2+kg)*192 + br)*12 + half*4)*4;
            cpa16(dst, src, 16);
        } else {                              // A: h(t-1) rows
            int a = slot - 1536;              // 0..511
            int plane = a >= 256;
            int rem = plane ? a - 256 : a;
            int kg = rem >= 128;
            int r2 = kg ? rem - 128 : rem;
            int r = r2 >> 1, half = r2 & 1;
            int sq = sq0 + r;
            int prow = sq*NF + t - 1; if (prow < 0) prow = 0;
            int sz = (t > 0 && sq < SEQ) ? 16 : 0;
            const __nv_bfloat16* src = (plane ? g_hsl : g_hsh)
                                       + (size_t)prow*HDIM + kc*32 + kg*16 + half*8;
            unsigned dst = sbase + (unsigned)((plane ? GR_AL : 0)
                                              + ((p*2+kg)*64 + r)*12 + half*4)*4;
            cpa16(dst, src, sz);
        }
    }
}

__global__ __launch_bounds__(256, 2) void k_gru(const float* __restrict__ gbias, int t) {
    extern __shared__ unsigned su[];
    const int tid = threadIdx.x;
    const int lane = tid & 31, wid = tid >> 5;
    const int wm = wid >> 2, wn = wid & 3;      // 2 x 4 warps: 32 rows x 48 cols each
    const int grp = lane >> 2, tig = lane & 3;
    const int g = blockIdx.x;                   // 0..3 hidden-col group
    const int sq0 = blockIdx.y * 64;
    unsigned sbase = (unsigned)__cvta_generic_to_shared(su);

    float acc[2][6][4] = {};
    grus_load(sbase, 0, 0, sq0, g, t);
    CPA_COMMIT(); CPA_WAIT(); __syncthreads();
    #pragma unroll 1
    for (int kc = 0; kc < 8; kc++) {
        int p = kc & 1, q = p ^ 1;
        if (kc + 1 < 8) { grus_load(sbase, q, kc+1, sq0, g, t); CPA_COMMIT(); }
        #pragma unroll
        for (int kg = 0; kg < 2; kg++) {
            int ab = (p*2+kg)*64;
            unsigned afh[2][4], afl[2][4];
            #pragma unroll
            for (int mt = 0; mt < 2; mt++) {
                int rA = ab + wm*32 + mt*16 + grp;
                afh[mt][0] = su[rA*12 + tig];
                afh[mt][1] = su[(rA+8)*12 + tig];
                afh[mt][2] = su[rA*12 + tig+4];
                afh[mt][3] = su[(rA+8)*12 + tig+4];
                afl[mt][0] = su[GR_AL + rA*12 + tig];
                afl[mt][1] = su[GR_AL + (rA+8)*12 + tig];
                afl[mt][2] = su[GR_AL + rA*12 + tig+4];
                afl[mt][3] = su[GR_AL + (rA+8)*12 + tig+4];
            }
            #pragma unroll
            for (int nt = 0; nt < 6; nt++) {
                int br = wn*48 + nt*8 + grp;
                int bb = ((p*2+kg)*192 + br)*12;
                unsigned bh0 = su[GR_BH + bb + tig];
                unsigned bh1 = su[GR_BH + bb + tig+4];
                unsigned bl0 = su[GR_BL + bb + tig];
                unsigned bl1 = su[GR_BL + bb + tig+4];
                #pragma unroll
                for (int mt = 0; mt < 2; mt++) {
                    mmab(acc[mt][nt], afh[mt], bh0, bh1);
                    mmab(acc[mt][nt], afh[mt], bl0, bl1);
                    mmab(acc[mt][nt], afl[mt], bh0, bh1);
                }
            }
        }
        if (kc + 1 < 8) CPA_WAIT();
        __syncthreads();
    }
    // stage hg floats [64][196] into B region (all mma reads complete)
    float* hg = (float*)(su + GR_BH);
    #pragma unroll
    for (int mt = 0; mt < 2; mt++) {
        #pragma unroll
        for (int nt = 0; nt < 6; nt++) {
            int r0 = wm*32 + mt*16 + grp;
            int c0 = wn*48 + nt*8 + 2*tig;
            hg[r0*196 + c0]       = acc[mt][nt][0];
            hg[r0*196 + c0+1]     = acc[mt][nt][1];
            hg[(r0+8)*196 + c0]   = acc[mt][nt][2];
            hg[(r0+8)*196 + c0+1] = acc[mt][nt][3];
        }
    }
    __syncthreads();
    // fused gates: 64 seqs x 64 hidden cols
    #pragma unroll
    for (int i = 0; i < 16; i++) {
        int e = tid + i*256;
        int s = e >> 6, cc = e & 63;
        int sq = sq0 + s;
        if (sq >= SEQ) continue;
        int c = g*64 + cc;
        const float* xg = g_xg + (size_t)(sq*NF + t)*N3H;
        float z = sigf_fast(xg[c]           + hg[s*196 + cc]        + gbias[c]);
        float r = sigf_fast(xg[HDIM + c]    + hg[s*196 + 64 + cc]   + gbias[HDIM + c]);
        float n = tanh_fast(xg[2*HDIM + c] + r*(hg[s*196 + 128 + cc] + gbias[2*HDIM + c]));
        float hp = 0.f;
        if (t > 0) {
            size_t pi = (size_t)(sq*NF + t - 1)*HDIM + c;
            hp = __bfloat162float(g_hsh[pi]) + __bfloat162float(g_hsl[pi]);
        }
        float h = (1.f - z)*n + z*hp;
        size_t gi = (size_t)(sq*NF + t)*HDIM + c;
        __nv_bfloat16 hh, hl;
        bsplit(h, hh, hl);
        g_hsh[gi] = hh; g_hsl[gi] = hl;
    }
}

// ---------------- modulate + inverse FFT (radix-4 core, 2 frames/block) ----------------
__global__ void k_modinv() {
    __shared__ float sre0[FBINS], sim0[FBINS], sre1[FBINS], sim1[FBINS];
    __shared__ float sr[NFFT], si[NFFT];
    __shared__ float twr[512], twi[512];
    const int pr  = blockIdx.x;
    const int tid = threadIdx.x;
    const int fr0 = 2*pr, fr1 = fr0 + 1;

    for (int k = tid; k < 512; k += 256) { twr[k] = g_twr[k]; twi[k] = g_twi[k]; }
    for (int k = tid; k < FBINS; k += 256) {
        float mag0 = __bfloat162float(g_magh[fr0*KPAD + k]) + __bfloat162float(g_magl[fr0*KPAD + k]);
        float mm0 = g_gb[(size_t)fr0*NGB + k]*mag0 + g_gb[(size_t)fr0*NGB + FBINS + k];
        sre0[k] = mm0 * g_cosp[fr0*FBINS + k];
        sim0[k] = mm0 * g_sinp[fr0*FBINS + k];
        float mag1 = __bfloat162float(g_magh[fr1*KPAD + k]) + __bfloat162float(g_magl[fr1*KPAD + k]);
        float mm1 = g_gb[(size_t)fr1*NGB + k]*mag1 + g_gb[(size_t)fr1*NGB + FBINS + k];
        sre1[k] = mm1 * g_cosp[fr1*FBINS + k];
        sim1[k] = mm1 * g_sinp[fr1*FBINS + k];
    }
    __syncthreads();
    for (int n = tid; n < NFFT; n += 256) {
        float zr, zi;
        if (n <= 512) { zr = sre0[n] - sim1[n];         zi = sim0[n] + sre1[n]; }
        else { int m = NFFT - n; zr = sre0[m] + sim1[m]; zi = sre1[m] - sim0[m]; }
        int j = __brev((unsigned)n) >> 22;
        sr[j] = zr; si[j] = zi;
    }
    __syncthreads();
    #pragma unroll
    for (int s = 1; s <= 9; s += 2) {
        const int h = 1 << (s-1);
        const int pos = tid & (h-1);
        const int grl = tid >> (s-1);
        const int base = (grl << (s+1)) + pos;
        const float wr1 = twr[pos << (10-s)], wi1 = -twi[pos << (10-s)];
        const float wr2 = twr[pos << (9-s)],  wi2 = -twi[pos << (9-s)];
        const int e3 = (pos + h) << (9-s);
        const float wr3 = twr[e3], wi3 = -twi[e3];
        float x0r = sr[base],       x0i = si[base];
        float x1r = sr[base+h],     x1i = si[base+h];
        float x2r = sr[base+2*h],   x2i = si[base+2*h];
        float x3r = sr[base+3*h],   x3i = si[base+3*h];
        float t1r = wr1*x1r - wi1*x1i, t1i = wr1*x1i + wi1*x1r;
        float u0r = x0r + t1r, u0i = x0i + t1i;
        float u1r = x0r - t1r, u1i = x0i - t1i;
        float t3r = wr1*x3r - wi1*x3i, t3i = wr1*x3i + wi1*x3r;
        float u2r = x2r + t3r, u2i = x2i + t3i;
        float u3r = x2r - t3r, u3i = x2i - t3i;
        float v2r = wr2*u2r - wi2*u2i, v2i = wr2*u2i + wi2*u2r;
        float v3r = wr3*u3r - wi3*u3i, v3i = wr3*u3i + wi3*u3r;
        sr[base]       = u0r + v2r; si[base]       = u0i + v2i;
        sr[base+2*h]   = u0r - v2r; si[base+2*h]   = u0i - v2i;
        sr[base+h]     = u1r + v3r; si[base+h]     = u1i + v3i;
        sr[base+3*h]   = u1r - v3r; si[base+3*h]   = u1i - v3i;
        __syncthreads();
    }
    const float invn = 1.f/(float)NFFT;
    for (int n = tid; n < NFFT; n += 256) {
        float w = invn*g_win[n];
        g_y[(size_t)fr0*NFFT + n] = sr[n]*w;
        g_y[(size_t)fr1*NFFT + n] = si[n]*w;
    }
}

// ---------------- overlap-add ----------------
__global__ void k_overlap(float* __restrict__ out) {
    const int t = blockIdx.x*blockDim.x + threadIdx.x;
    const int b = blockIdx.y;
    if (t >= TSZ) return;
    int ci_hi = t / STRIDE; if (ci_hi > NCH-1) ci_hi = NCH-1;
    int v = t - (CHUNK - 1);
    int ci_lo = (v <= 0) ? 0 : (v + STRIDE - 1)/STRIDE;
    float acc = 0.f;
    for (int ci = ci_lo; ci <= ci_hi; ci++) {
        int n = t - ci*STRIDE;
        int fi_hi = n >> 8; if (fi_hi > NF-1) fi_hi = NF-1;
        int w = n - (NFFT - 1);
        int fi_lo = (w <= 0) ? 0 : (w + HOP - 1) >> 8;
        float s = 0.f;
        for (int fi = fi_lo; fi <= fi_hi; fi++)
            s += g_y[(size_t)(((b*NCH + ci)*NF) + fi)*NFFT + n - fi*HOP];
        acc += s / fmaxf(g_wsum[n], 1e-8f);
    }
    out[b*TSZ + t] = acc;
}

// ---------------- launch ----------------
extern "C" void kernel_launch(void* const* d_in, const int* in_sizes, int n_in,
                              void* d_out, int out_size) {
    const float* audio     = (const float*)d_in[0];
    const float* emb_table = (const float*)d_in[1];
    const float* gru_wx    = (const float*)d_in[2];
    const float* gru_wh    = (const float*)d_in[3];
    const float* gru_b     = (const float*)d_in[4];
    const float* proj_w    = (const float*)d_in[5];
    const float* proj_b    = (const float*)d_in[6];
    const int*   effect_id = (const int*)  d_in[7];
    float* out = (float*)d_out;

    cudaFuncSetAttribute(k_gru, cudaFuncAttributeMaxDynamicSharedMemorySize,
                         GRUS_SMEM_BYTES);   // idempotent host-side call

    k_prep<<<PB_TAB + PB_WX + PB_PW + PB_WH + BATCH, 256>>>(
        gru_wx, proj_w, gru_wh, emb_table, effect_id);                        // 1
    k_fwdfft<<<ROWS/2, 256>>>(audio);                                         // 2
    k_xg<<<dim3(N3H/128, (ROWS + 127)/128), 256, SMEM_GEMM_BYTES>>>();        // 3
    for (int t = 0; t < NF; t++)                                              // 4.. (slot 4 = t=0)
        k_gru<<<dim3(4, (SEQ + 63)/64), 256, GRUS_SMEM_BYTES>>>(gru_b, t);
    k_proj<<<dim3(PWLD/128, (ROWS + 127)/128), 256, SMEM_GEMM_BYTES>>>(proj_b);
    k_modinv<<<ROWS/2, 256>>>();
    k_overlap<<<dim3((TSZ + 255)/256, BATCH), 256>>>(out);
}

// round 12
// speedup vs baseline: 1.2402x; 1.2402x over previous
#include <cuda_runtime.h>
#include <cuda_bf16.h>
#include <math.h>

// ---------------- problem constants ----------------
#define TSZ    480000
#define BATCH  8
#define CHUNK  4096
#define STRIDE 3072
#define NCH    157
#define NF     13
#define NFFT   1024
#define HOP    256
#define FBINS  513
#define HDIM   256
#define EDIM   128
#define N3H    768
#define SEQ    (BATCH*NCH)   // 1256
#define ROWS   (SEQ*NF)      // 16328
#define CPB    (NCH*NF)      // 2041
#define KPAD   528
#define PWLD   1152
#define NGB    1026
#define NTILE  40            // GRU seq tiles of 32
#define PI_F   3.14159265358979323846f

// ---------------- scratch ----------------
__device__ __nv_bfloat16 g_magh[ROWS*KPAD], g_magl[ROWS*KPAD];
__device__ float g_cosp[ROWS*FBINS];
__device__ float g_sinp[ROWS*FBINS];
__device__ float g_xg  [ROWS*N3H];
__device__ __nv_bfloat16 g_hsh[ROWS*HDIM], g_hsl[ROWS*HDIM];
__device__ float g_gb  [ROWS*NGB];
__device__ float g_y   [ROWS*NFFT];
__device__ float g_embrow[BATCH*N3H];
__device__ float g_wsum[CHUNK];
__device__ __nv_bfloat16 g_wxh[N3H*KPAD], g_wxl[N3H*KPAD];   // [n][k]
__device__ __nv_bfloat16 g_pwh[PWLD*HDIM], g_pwl[PWLD*HDIM]; // [n][k]
// GRU weights pre-padded in smem tile format: [g(4)][kc(8)][plane(2)][kg(2)][192][12] uints
#define GW_CH 9216
__device__ unsigned g_wpad[4*8*GW_CH];
// GRU h in padded ping-pong tile format: [parity(2)][tile(40)][kc(8)][plane(2)][kg(2)][32][12]
#define GA_CH 1536
__device__ unsigned g_hpad[2*NTILE*8*GA_CH];
__device__ float g_twr[512], g_twi[512];
__device__ float g_win[NFFT];

__device__ __forceinline__ float sigf_fast(float x) { return 1.f/(1.f + __expf(-x)); }
__device__ __forceinline__ float tanh_fast(float x) { return 2.f/(1.f + __expf(-2.f*x)) - 1.f; }

__device__ __forceinline__ void bsplit(float v, __nv_bfloat16& h, __nv_bfloat16& l) {
    h = __float2bfloat16(v);
    l = __float2bfloat16(v - __bfloat162float(h));
}

__device__ __forceinline__ void mmab(float* c, const unsigned* a, unsigned b0, unsigned b1) {
    asm volatile("mma.sync.aligned.m16n8k16.row.col.f32.bf16.bf16.f32 "
        "{%0,%1,%2,%3}, {%4,%5,%6,%7}, {%8,%9}, {%0,%1,%2,%3};"
        : "+f"(c[0]), "+f"(c[1]), "+f"(c[2]), "+f"(c[3])
        : "r"(a[0]), "r"(a[1]), "r"(a[2]), "r"(a[3]), "r"(b0), "r"(b1));
}
__device__ __forceinline__ void cpa16(unsigned d, const void* s, int sz) {
    asm volatile("cp.async.ca.shared.global [%0], [%1], 16, %2;" :: "r"(d), "l"(s), "r"(sz));
}
#define CPA_COMMIT() asm volatile("cp.async.commit_group;")
#define CPA_WAIT()   asm volatile("cp.async.wait_all;" ::: "memory")

__device__ __forceinline__ void cpbulk(unsigned dst, const void* src, unsigned bytes, unsigned mbar) {
    asm volatile("cp.async.bulk.shared::cta.global.mbarrier::complete_tx::bytes "
                 "[%0], [%1], %2, [%3];"
                 :: "r"(dst), "l"(src), "r"(bytes), "r"(mbar) : "memory");
}
__device__ __forceinline__ void mbar_wait(unsigned mbar, unsigned parity) {
    unsigned done = 0;
    while (!done) {
        asm volatile("{\n\t.reg .pred p;\n\t"
            "mbarrier.try_wait.parity.acquire.cta.shared::cta.b64 p, [%1], %2;\n\t"
            "selp.b32 %0, 1, 0, p;\n\t}"
            : "=r"(done) : "r"(mbar), "r"(parity) : "memory");
    }
}

// ---------------- merged prep ----------------
#define PB_TAB 16
#define PB_WX  1584   // N3H*KPAD/256
#define PB_PW  1152   // PWLD*HDIM/256
#define PB_WP  1152   // 4*8*GW_CH/256
__global__ void k_prep(const float* __restrict__ wx,
                       const float* __restrict__ pw,
                       const float* __restrict__ wh,
                       const float* __restrict__ emb_table,
                       const int*   __restrict__ effect_id) {
    __shared__ float se[EDIM];
    const int bx = blockIdx.x, tid = threadIdx.x;
    if (bx < PB_TAB) {
        int i = bx*256 + tid;
        if (i < 512) {
            float s, c; sincosf(-(2.f*PI_F/NFFT)*i, &s, &c);
            g_twr[i] = c; g_twi[i] = s;
        }
        if (i < NFFT)
            g_win[i] = 0.5f - 0.5f*cosf((2.f*PI_F/NFFT)*i);
        if (i < CHUNK) {
            float ws = 0.f;
            for (int fi = 0; fi < NF; fi++) {
                int d = i - fi*HOP;
                if (d >= 0 && d < NFFT) {
                    float w = 0.5f - 0.5f*cosf((2.f*PI_F/NFFT)*d);
                    ws += w*w;
                }
            }
            g_wsum[i] = ws;
        }
    } else if (bx < PB_TAB + PB_WX) {
        int i = (bx - PB_TAB)*256 + tid;
        int n = i / KPAD, k = i % KPAD;
        float v = (k < FBINS) ? wx[(size_t)k*N3H + n] : 0.f;
        bsplit(v, g_wxh[i], g_wxl[i]);
    } else if (bx < PB_TAB + PB_WX + PB_PW) {
        int j = (bx - PB_TAB - PB_WX)*256 + tid;
        int n = j / HDIM, k = j % HDIM;
        float v = (n < NGB) ? pw[(size_t)k*NGB + n] : 0.f;
        bsplit(v, g_pwh[j], g_pwl[j]);
    } else if (bx < PB_TAB + PB_WX + PB_PW + PB_WP) {
        int j = (bx - PB_TAB - PB_WX - PB_PW)*256 + tid;   // 0..294911
        int g = j / 73728;
        int r1 = j % 73728;
        int kc = r1 / GW_CH;
        int r2 = r1 % GW_CH;
        int plane = r2 / 4608;
        int r3 = r2 % 4608;
        int kg = r3 / 2304;
        int r4 = r3 % 2304;
        int br = r4 / 12;
        int u  = r4 % 12;
        unsigned val = 0;
        if (u < 8) {
            int k = kc*32 + kg*16 + u*2;
            int n = ((br >> 6) << 8) + g*64 + (br & 63);
            float v0 = wh[(size_t)k*N3H + n];
            float v1 = wh[(size_t)(k+1)*N3H + n];
            __nv_bfloat16 h0, l0, h1, l1;
            bsplit(v0, h0, l0); bsplit(v1, h1, l1);
            unsigned lo16, hi16;
            if (plane == 0) { lo16 = __bfloat16_as_ushort(h0); hi16 = __bfloat16_as_ushort(h1); }
            else            { lo16 = __bfloat16_as_ushort(l0); hi16 = __bfloat16_as_ushort(l1); }
            val = (hi16 << 16) | lo16;
        }
        g_wpad[j] = val;
    } else {
        int b = bx - PB_TAB - PB_WX - PB_PW - PB_WP;   // 0..7
        if (tid < EDIM) se[tid] = emb_table[effect_id[b]*EDIM + tid];
        __syncthreads();
        for (int j = tid; j < N3H; j += 256) {
            float acc = 0.f;
            #pragma unroll 8
            for (int k = 0; k < EDIM; k++)
                acc += se[k] * wx[(size_t)(FBINS + k)*N3H + j];
            g_embrow[b*N3H + j] = acc;
        }
    }
}

// ---------------- forward STFT: 2 real frames per complex FFT, radix-4 core ----------------
__global__ void k_fwdfft(const float* __restrict__ audio) {
    __shared__ float sr[NFFT], si[NFFT];
    __shared__ float twr[512], twi[512];
    const int pr  = blockIdx.x;
    const int tid = threadIdx.x;
    const int fr0 = 2*pr, fr1 = fr0 + 1;
    const int b0 = fr0 / CPB, r0 = fr0 % CPB;
    const int b1 = fr1 / CPB, r1 = fr1 % CPB;
    const int base0 = (r0/NF)*STRIDE + (r0%NF)*HOP;
    const int base1 = (r1/NF)*STRIDE + (r1%NF)*HOP;

    for (int k = tid; k < 512; k += 256) { twr[k] = g_twr[k]; twi[k] = g_twi[k]; }
    for (int n = tid; n < NFFT; n += 256) {
        int s0 = base0 + n, s1 = base1 + n;
        float v0 = (s0 < TSZ) ? audio[b0*TSZ + s0] : 0.f;
        float v1 = (s1 < TSZ) ? audio[b1*TSZ + s1] : 0.f;
        float w = g_win[n];
        int j = __brev((unsigned)n) >> 22;
        sr[j] = v0*w; si[j] = v1*w;
    }
    __syncthreads();
    #pragma unroll
    for (int s = 1; s <= 9; s += 2) {
        const int h = 1 << (s-1);
        const int pos = tid & (h-1);
        const int grl = tid >> (s-1);
        const int base = (grl << (s+1)) + pos;
        const float wr1 = twr[pos << (10-s)], wi1 = twi[pos << (10-s)];
        const float wr2 = twr[pos << (9-s)],  wi2 = twi[pos << (9-s)];
        const int e3 = (pos + h) << (9-s);
        const float wr3 = twr[e3], wi3 = twi[e3];
        float x0r = sr[base],       x0i = si[base];
        float x1r = sr[base+h],     x1i = si[base+h];
        float x2r = sr[base+2*h],   x2i = si[base+2*h];
        float x3r = sr[base+3*h],   x3i = si[base+3*h];
        float t1r = wr1*x1r - wi1*x1i, t1i = wr1*x1i + wi1*x1r;
        float u0r = x0r + t1r, u0i = x0i + t1i;
        float u1r = x0r - t1r, u1i = x0i - t1i;
        float t3r = wr1*x3r - wi1*x3i, t3i = wr1*x3i + wi1*x3r;
        float u2r = x2r + t3r, u2i = x2i + t3i;
        float u3r = x2r - t3r, u3i = x2i - t3i;
        float v2r = wr2*u2r - wi2*u2i, v2i = wr2*u2i + wi2*u2r;
        float v3r = wr3*u3r - wi3*u3i, v3i = wr3*u3i + wi3*u3r;
        sr[base]       = u0r + v2r; si[base]       = u0i + v2i;
        sr[base+2*h]   = u0r - v2r; si[base+2*h]   = u0i - v2i;
        sr[base+h]     = u1r + v3r; si[base+h]     = u1i + v3i;
        sr[base+3*h]   = u1r - v3r; si[base+3*h]   = u1i - v3i;
        __syncthreads();
    }
    for (int k = tid; k < KPAD; k += 256) {
        if (k < FBINS) {
            int m = (NFFT - k) & (NFFT-1);
            float rek = sr[k], imk = si[k];
            float rem = sr[m], imm = si[m];
            float re0 = 0.5f*(rek + rem), i0 = 0.5f*(imk - imm);
            float re1 = 0.5f*(imk + imm), i1 = 0.5f*(rem - rek);
            float mag0 = sqrtf(re0*re0 + i0*i0);
            float c0, s0;
            if (mag0 > 1e-30f) { float inv = 1.f/mag0; c0 = re0*inv; s0 = i0*inv; }
            else               { c0 = 1.f; s0 = 0.f; }
            float mag1 = sqrtf(re1*re1 + i1*i1);
            float c1, s1;
            if (mag1 > 1e-30f) { float inv = 1.f/mag1; c1 = re1*inv; s1 = i1*inv; }
            else               { c1 = 1.f; s1 = 0.f; }
            bsplit(mag0, g_magh[fr0*KPAD + k], g_magl[fr0*KPAD + k]);
            bsplit(mag1, g_magh[fr1*KPAD + k], g_magl[fr1*KPAD + k]);
            g_cosp[fr0*FBINS + k] = c0; g_sinp[fr0*FBINS + k] = s0;
            g_cosp[fr1*FBINS + k] = c1; g_sinp[fr1*FBINS + k] = s1;
        } else {
            __nv_bfloat16 z = __float2bfloat16(0.f);
            g_magh[fr0*KPAD + k] = z; g_magl[fr0*KPAD + k] = z;
            g_magh[fr1*KPAD + k] = z; g_magl[fr1*KPAD + k] = z;
        }
    }
}

// ================= bf16-split 3-pass tensor GEMM (validated) =================
#define SM_PLANE (128*12)
#define SM_AH(p,r,c) smem_u[((p)*128 + (r))*12 + (c)]
#define SM_AL(p,r,c) smem_u[SM_PLANE*2 + ((p)*128 + (r))*12 + (c)]
#define SM_BH(p,r,c) smem_u[SM_PLANE*4 + ((p)*128 + (r))*12 + (c)]
#define SM_BL(p,r,c) smem_u[SM_PLANE*6 + ((p)*128 + (r))*12 + (c)]
#define SMEM_GEMM_BYTES (SM_PLANE*8*4)   // 49152

template<int NIT, int KSTRIDE>
__device__ __forceinline__ void gemm_core(
    unsigned* smem_u,
    const __nv_bfloat16* Ah_g, const __nv_bfloat16* Al_g, int a_row_max,
    const __nv_bfloat16* Bh_g, const __nv_bfloat16* Bl_g,
    int m0, int n0, float acc[2][8][4])
{
    const int tid = threadIdx.x;
    const int lane = tid & 31, wid = tid >> 5;
    const int wm = wid >> 1, wn = wid & 1;
    const int grp = lane >> 2, tig = lane & 3;
    const int row = tid >> 1, half = tid & 1;
    const int arow = m0 + row;
    const int asz = (arow < a_row_max) ? 16 : 0;
    const int brow = n0 + row;

    unsigned sbase = (unsigned)__cvta_generic_to_shared(smem_u);
    unsigned off = (row*12 + half*4)*4;
    unsigned dAh = sbase + off;
    unsigned dAl = sbase + SM_PLANE*2*4 + off;
    unsigned dBh = sbase + SM_PLANE*4*4 + off;
    unsigned dBl = sbase + SM_PLANE*6*4 + off;
    const unsigned bufB = 128*12*4;

    cpa16(dAh, Ah_g + (size_t)arow*KSTRIDE + half*8, asz);
    cpa16(dAl, Al_g + (size_t)arow*KSTRIDE + half*8, asz);
    cpa16(dBh, Bh_g + (size_t)brow*KSTRIDE + half*8, 16);
    cpa16(dBl, Bl_g + (size_t)brow*KSTRIDE + half*8, 16);
    CPA_COMMIT();
    CPA_WAIT();
    __syncthreads();

    #pragma unroll 1
    for (int it = 0; it < NIT; it++) {
        int p = it & 1, q = p ^ 1;
        if (it + 1 < NIT) {
            int k0 = (it+1)*16;
            cpa16(dAh + q*bufB, Ah_g + (size_t)arow*KSTRIDE + k0 + half*8, asz);
            cpa16(dAl + q*bufB, Al_g + (size_t)arow*KSTRIDE + k0 + half*8, asz);
            cpa16(dBh + q*bufB, Bh_g + (size_t)brow*KSTRIDE + k0 + half*8, 16);
            cpa16(dBl + q*bufB, Bl_g + (size_t)brow*KSTRIDE + k0 + half*8, 16);
            CPA_COMMIT();
        }
        unsigned afh[2][4], afl[2][4];
        #pragma unroll
        for (int mt = 0; mt < 2; mt++) {
            int rA = wm*32 + mt*16 + grp;
            afh[mt][0] = SM_AH(p, rA,   tig);
            afh[mt][1] = SM_AH(p, rA+8, tig);
            afh[mt][2] = SM_AH(p, rA,   tig+4);
            afh[mt][3] = SM_AH(p, rA+8, tig+4);
            afl[mt][0] = SM_AL(p, rA,   tig);
            afl[mt][1] = SM_AL(p, rA+8, tig);
            afl[mt][2] = SM_AL(p, rA,   tig+4);
            afl[mt][3] = SM_AL(p, rA+8, tig+4);
        }
        #pragma unroll
        for (int nt = 0; nt < 8; nt++) {
            int cB = wn*64 + nt*8 + grp;
            unsigned bh0 = SM_BH(p, cB, tig);
            unsigned bh1 = SM_BH(p, cB, tig+4);
            unsigned bl0 = SM_BL(p, cB, tig);
            unsigned bl1 = SM_BL(p, cB, tig+4);
            #pragma unroll
            for (int mt = 0; mt < 2; mt++) {
                mmab(acc[mt][nt], afh[mt], bh0, bh1);
                mmab(acc[mt][nt], afh[mt], bl0, bl1);
                mmab(acc[mt][nt], afl[mt], bh0, bh1);
            }
        }
        if (it + 1 < NIT) CPA_WAIT();
        __syncthreads();
    }
}

// ---- k_xg ----
__global__ __launch_bounds__(256, 2) void k_xg() {
    extern __shared__ unsigned smem_u[];
    const int tid = threadIdx.x;
    const int lane = tid & 31, wid = tid >> 5;
    const int wm = wid >> 1, wn = wid & 1;
    const int grp = lane >> 2, tig = lane & 3;
    const int m0 = blockIdx.y * 128, n0 = blockIdx.x * 128;
    float acc[2][8][4] = {};
    gemm_core<33, KPAD>(smem_u, g_magh, g_magl, ROWS, g_wxh, g_wxl, m0, n0, acc);
    #pragma unroll
    for (int mt = 0; mt < 2; mt++) {
        #pragma unroll
        for (int nt = 0; nt < 8; nt++) {
            int row0 = m0 + wm*32 + mt*16 + grp;
            int col0 = n0 + wn*64 + nt*8 + 2*tig;
            if (row0 < ROWS) {
                int b = row0 / CPB;
                g_xg[(size_t)row0*N3H + col0  ] = acc[mt][nt][0] + g_embrow[b*N3H + col0  ];
                g_xg[(size_t)row0*N3H + col0+1] = acc[mt][nt][1] + g_embrow[b*N3H + col0+1];
            }
            int row1 = row0 + 8;
            if (row1 < ROWS) {
                int b = row1 / CPB;
                g_xg[(size_t)row1*N3H + col0  ] = acc[mt][nt][2] + g_embrow[b*N3H + col0  ];
                g_xg[(size_t)row1*N3H + col0+1] = acc[mt][nt][3] + g_embrow[b*N3H + col0+1];
            }
        }
    }
}

// ---- k_proj ----
__global__ __launch_bounds__(256, 2) void k_proj(const float* __restrict__ pb) {
    extern __shared__ unsigned smem_u[];
    const int tid = threadIdx.x;
    const int lane = tid & 31, wid = tid >> 5;
    const int wm = wid >> 1, wn = wid & 1;
    const int grp = lane >> 2, tig = lane & 3;
    const int m0 = blockIdx.y * 128, n0 = blockIdx.x * 128;
    float acc[2][8][4] = {};
    gemm_core<16, HDIM>(smem_u, g_hsh, g_hsl, ROWS, g_pwh, g_pwl, m0, n0, acc);
    #pragma unroll
    for (int mt = 0; mt < 2; mt++) {
        #pragma unroll
        for (int nt = 0; nt < 8; nt++) {
            int row0 = m0 + wm*32 + mt*16 + grp;
            int col0 = n0 + wn*64 + nt*8 + 2*tig;
            if (row0 < ROWS) {
                if (col0   < NGB) g_gb[(size_t)row0*NGB + col0  ] = acc[mt][nt][0] + pb[col0  ];
                if (col0+1 < NGB) g_gb[(size_t)row0*NGB + col0+1] = acc[mt][nt][1] + pb[col0+1];
            }
            int row1 = row0 + 8;
            if (row1 < ROWS) {
                if (col0   < NGB) g_gb[(size_t)row1*NGB + col0  ] = acc[mt][nt][2] + pb[col0  ];
                if (col0+1 < NGB) g_gb[(size_t)row1*NGB + col0+1] = acc[mt][nt][3] + pb[col0+1];
            }
        }
    }
}

// ================= per-step GRU with cp.async.bulk (32 seqs x 192 cols, BK=32) =================
// grid (4, 40) = 160 blocks, 2 blocks/SM. smem (uints):
//   B [2buf][plane(2)][kg(2)][192][12] @0        (2*9216)
//   A [2buf][plane(2)][kg(2)][32][12]  @18432    (2*1536)
//   mbar[2] @21504..21507. Total 21508 u -> 86048 bytes alloc.
// hg staging floats [32][196] aliases B after final sync.
#define GB_BUF 9216
#define GB_A0  18432
#define GA_BUF 1536
#define GMB    21504
#define GRUS_SMEM_BYTES 86048

__device__ __forceinline__ void gru_issue(unsigned sbase, int buf, int kc,
                                          int g, int tile, int t) {
    unsigned mbar = sbase + (GMB + buf*2)*4;
    unsigned bytes = (t > 0) ? (36864u + 6144u) : 36864u;
    asm volatile("mbarrier.arrive.expect_tx.shared.b64 _, [%0], %1;"
                 :: "r"(mbar), "r"(bytes) : "memory");
    cpbulk(sbase + (unsigned)(buf*GB_BUF)*4,
           g_wpad + ((size_t)g*8 + kc)*GW_CH, 36864u, mbar);
    if (t > 0)
        cpbulk(sbase + (unsigned)(GB_A0 + buf*GA_BUF)*4,
               g_hpad + (((size_t)((t-1)&1)*NTILE + tile)*8 + kc)*GA_CH, 6144u, mbar);
}

__global__ __launch_bounds__(256, 2) void k_gru(const float* __restrict__ gbias, int t) {
    extern __shared__ unsigned su[];
    const int tid = threadIdx.x;
    const int lane = tid & 31, wid = tid >> 5;
    const int wm = wid >> 2, wn = wid & 3;      // 2 x 4 warps: 16 rows x 48 cols
    const int grp = lane >> 2, tig = lane & 3;
    const int g = blockIdx.x, tile = blockIdx.y;
    const int sq0 = tile*32;
    unsigned sbase = (unsigned)__cvta_generic_to_shared(su);
    const unsigned mb0 = sbase + GMB*4, mb1 = sbase + (GMB+2)*4;

    if (tid == 0) {
        asm volatile("mbarrier.init.shared.b64 [%0], 1;" :: "r"(mb0) : "memory");
        asm volatile("mbarrier.init.shared.b64 [%0], 1;" :: "r"(mb1) : "memory");
    }
    if (t == 0)
        for (int i = tid; i < 2*GA_BUF; i += 256) su[GB_A0 + i] = 0;
    __syncthreads();
    if (tid == 0) { gru_issue(sbase, 0, 0, g, tile, t); gru_issue(sbase, 1, 1, g, tile, t); }

    float acc[6][4] = {};
    #pragma unroll 1
    for (int kc = 0; kc < 8; kc++) {
        int b = kc & 1;
        mbar_wait(b ? mb1 : mb0, (kc >> 1) & 1);
        #pragma unroll
        for (int kg = 0; kg < 2; kg++) {
            int Ab = GB_A0 + b*GA_BUF + kg*384;
            int rA = wm*16 + grp;
            unsigned afh[4], afl[4];
            afh[0] = su[Ab + rA*12 + tig];
            afh[1] = su[Ab + (rA+8)*12 + tig];
            afh[2] = su[Ab + rA*12 + tig+4];
            afh[3] = su[Ab + (rA+8)*12 + tig+4];
            afl[0] = su[Ab + 768 + rA*12 + tig];
            afl[1] = su[Ab + 768 + (rA+8)*12 + tig];
            afl[2] = su[Ab + 768 + rA*12 + tig+4];
            afl[3] = su[Ab + 768 + (rA+8)*12 + tig+4];
            #pragma unroll
            for (int nt = 0; nt < 6; nt++) {
                int Bb = b*GB_BUF + kg*2304 + (wn*48 + nt*8 + grp)*12;
                unsigned bh0 = su[Bb + tig];
                unsigned bh1 = su[Bb + tig+4];
                unsigned bl0 = su[Bb + 4608 + tig];
                unsigned bl1 = su[Bb + 4608 + tig+4];
                mmab(acc[nt], afh, bh0, bh1);
                mmab(acc[nt], afh, bl0, bl1);
                mmab(acc[nt], afl, bh0, bh1);
            }
        }
        __syncthreads();
        if (kc + 2 < 8 && tid == 0) gru_issue(sbase, b, kc+2, g, tile, t);
    }
    // stage hg floats [32][196] over B region (all mma reads complete)
    float* hg = (float*)su;
    #pragma unroll
    for (int nt = 0; nt < 6; nt++) {
        int r0 = wm*16 + grp, c0 = wn*48 + nt*8 + 2*tig;
        hg[r0*196 + c0]       = acc[nt][0];
        hg[r0*196 + c0+1]     = acc[nt][1];
        hg[(r0+8)*196 + c0]   = acc[nt][2];
        hg[(r0+8)*196 + c0+1] = acc[nt][3];
    }
    __syncthreads();
    // fused gates: 32 seqs x 64 hidden cols
    __nv_bfloat16* hpB = (__nv_bfloat16*)g_hpad;
    #pragma unroll
    for (int i = 0; i < 8; i++) {
        int e = tid + i*256;
        int s = e >> 6, cc = e & 63;
        int sq = sq0 + s;
        if (sq >= SEQ) continue;
        int c = g*64 + cc;
        const float* xg = g_xg + (size_t)(sq*NF + t)*N3H;
        float z = sigf_fast(xg[c]           + hg[s*196 + cc]        + gbias[c]);
        float r = sigf_fast(xg[HDIM + c]    + hg[s*196 + 64 + cc]   + gbias[HDIM + c]);
        float n = tanh_fast(xg[2*HDIM + c] + r*(hg[s*196 + 128 + cc] + gbias[2*HDIM + c]));
        float hp = 0.f;
        if (t > 0) {
            size_t pi = (size_t)(sq*NF + t - 1)*HDIM + c;
            hp = __bfloat162float(g_hsh[pi]) + __bfloat162float(g_hsl[pi]);
        }
        float h = (1.f - z)*n + z*hp;
        __nv_bfloat16 hh, hl;
        bsplit(h, hh, hl);
        size_t gi = (size_t)(sq*NF + t)*HDIM + c;
        g_hsh[gi] = hh; g_hsl[gi] = hl;
        // padded ping-pong write for next step's bulk load
        int kc2 = c >> 5, kg2 = (c >> 4) & 1, u2 = (c & 15) >> 1, hf = c & 1;
        size_t ub = (((size_t)(t&1)*NTILE + tile)*8 + kc2)*GA_CH + kg2*384 + s*12 + u2;
        hpB[ub*2 + hf]         = hh;
        hpB[(ub + 768)*2 + hf] = hl;
    }
}

// ---------------- modulate + inverse FFT (radix-4 core, 2 frames/block) ----------------
__global__ void k_modinv() {
    __shared__ float sre0[FBINS], sim0[FBINS], sre1[FBINS], sim1[FBINS];
    __shared__ float sr[NFFT], si[NFFT];
    __shared__ float twr[512], twi[512];
    const int pr  = blockIdx.x;
    const int tid = threadIdx.x;
    const int fr0 = 2*pr, fr1 = fr0 + 1;

    for (int k = tid; k < 512; k += 256) { twr[k] = g_twr[k]; twi[k] = g_twi[k]; }
    for (int k = tid; k < FBINS; k += 256) {
        float mag0 = __bfloat162float(g_magh[fr0*KPAD + k]) + __bfloat162float(g_magl[fr0*KPAD + k]);
        float mm0 = g_gb[(size_t)fr0*NGB + k]*mag0 + g_gb[(size_t)fr0*NGB + FBINS + k];
        sre0[k] = mm0 * g_cosp[fr0*FBINS + k];
        sim0[k] = mm0 * g_sinp[fr0*FBINS + k];
        float mag1 = __bfloat162float(g_magh[fr1*KPAD + k]) + __bfloat162float(g_magl[fr1*KPAD + k]);
        float mm1 = g_gb[(size_t)fr1*NGB + k]*mag1 + g_gb[(size_t)fr1*NGB + FBINS + k];
        sre1[k] = mm1 * g_cosp[fr1*FBINS + k];
        sim1[k] = mm1 * g_sinp[fr1*FBINS + k];
    }
    __syncthreads();
    for (int n = tid; n < NFFT; n += 256) {
        float zr, zi;
        if (n <= 512) { zr = sre0[n] - sim1[n];         zi = sim0[n] + sre1[n]; }
        else { int m = NFFT - n; zr = sre0[m] + sim1[m]; zi = sre1[m] - sim0[m]; }
        int j = __brev((unsigned)n) >> 22;
        sr[j] = zr; si[j] = zi;
    }
    __syncthreads();
    #pragma unroll
    for (int s = 1; s <= 9; s += 2) {
        const int h = 1 << (s-1);
        const int pos = tid & (h-1);
        const int grl = tid >> (s-1);
        const int base = (grl << (s+1)) + pos;
        const float wr1 = twr[pos << (10-s)], wi1 = -twi[pos << (10-s)];
        const float wr2 = twr[pos << (9-s)],  wi2 = -twi[pos << (9-s)];
        const int e3 = (pos + h) << (9-s);
        const float wr3 = twr[e3], wi3 = -twi[e3];
        float x0r = sr[base],       x0i = si[base];
        float x1r = sr[base+h],     x1i = si[base+h];
        float x2r = sr[base+2*h],   x2i = si[base+2*h];
        float x3r = sr[base+3*h],   x3i = si[base+3*h];
        float t1r = wr1*x1r - wi1*x1i, t1i = wr1*x1i + wi1*x1r;
        float u0r = x0r + t1r, u0i = x0i + t1i;
        float u1r = x0r - t1r, u1i = x0i - t1i;
        float t3r = wr1*x3r - wi1*x3i, t3i = wr1*x3i + wi1*x3r;
        float u2r = x2r + t3r, u2i = x2i + t3i;
        float u3r = x2r - t3r, u3i = x2i - t3i;
        float v2r = wr2*u2r - wi2*u2i, v2i = wr2*u2i + wi2*u2r;
        float v3r = wr3*u3r - wi3*u3i, v3i = wr3*u3i + wi3*u3r;
        sr[base]       = u0r + v2r; si[base]       = u0i + v2i;
        sr[base+2*h]   = u0r - v2r; si[base+2*h]   = u0i - v2i;
        sr[base+h]     = u1r + v3r; si[base+h]     = u1i + v3i;
        sr[base+3*h]   = u1r - v3r; si[base+3*h]   = u1i - v3i;
        __syncthreads();
    }
    const float invn = 1.f/(float)NFFT;
    for (int n = tid; n < NFFT; n += 256) {
        float w = invn*g_win[n];
        g_y[(size_t)fr0*NFFT + n] = sr[n]*w;
        g_y[(size_t)fr1*NFFT + n] = si[n]*w;
    }
}

// ---------------- overlap-add ----------------
__global__ void k_overlap(float* __restrict__ out) {
    const int t = blockIdx.x*blockDim.x + threadIdx.x;
    const int b = blockIdx.y;
    if (t >= TSZ) return;
    int ci_hi = t / STRIDE; if (ci_hi > NCH-1) ci_hi = NCH-1;
    int v = t - (CHUNK - 1);
    int ci_lo = (v <= 0) ? 0 : (v + STRIDE - 1)/STRIDE;
    float acc = 0.f;
    for (int ci = ci_lo; ci <= ci_hi; ci++) {
        int n = t - ci*STRIDE;
        int fi_hi = n >> 8; if (fi_hi > NF-1) fi_hi = NF-1;
        int w = n - (NFFT - 1);
        int fi_lo = (w <= 0) ? 0 : (w + HOP - 1) >> 8;
        float s = 0.f;
        for (int fi = fi_lo; fi <= fi_hi; fi++)
            s += g_y[(size_t)(((b*NCH + ci)*NF) + fi)*NFFT + n - fi*HOP];
        acc += s / fmaxf(g_wsum[n], 1e-8f);
    }
    out[b*TSZ + t] = acc;
}

// ---------------- launch ----------------
extern "C" void kernel_launch(void* const* d_in, const int* in_sizes, int n_in,
                              void* d_out, int out_size) {
    const float* audio     = (const float*)d_in[0];
    const float* emb_table = (const float*)d_in[1];
    const float* gru_wx    = (const float*)d_in[2];
    const float* gru_wh    = (const float*)d_in[3];
    const float* gru_b     = (const float*)d_in[4];
    const float* proj_w    = (const float*)d_in[5];
    const float* proj_b    = (const float*)d_in[6];
    const int*   effect_id = (const int*)  d_in[7];
    float* out = (float*)d_out;

    cudaFuncSetAttribute(k_gru, cudaFuncAttributeMaxDynamicSharedMemorySize,
                         GRUS_SMEM_BYTES);   // idempotent host-side call

    k_prep<<<PB_TAB + PB_WX + PB_PW + PB_WP + BATCH, 256>>>(
        gru_wx, proj_w, gru_wh, emb_table, effect_id);                        // 1
    k_fwdfft<<<ROWS/2, 256>>>(audio);                                         // 2
    k_xg<<<dim3(N3H/128, (ROWS + 127)/128), 256, SMEM_GEMM_BYTES>>>();        // 3
    for (int t = 0; t < NF; t++)                                              // 4.. (slot 4 = t=0)
        k_gru<<<dim3(4, NTILE), 256, GRUS_SMEM_BYTES>>>(gru_b, t);
    k_proj<<<dim3(PWLD/128, (ROWS + 127)/128), 256, SMEM_GEMM_BYTES>>>(proj_b);
    k_modinv<<<ROWS/2, 256>>>();
    k_overlap<<<dim3((TSZ + 255)/256, BATCH), 256>>>(out);
}

// round 13
// speedup vs baseline: 1.2493x; 1.0073x over previous
#include <cuda_runtime.h>
#include <cuda_bf16.h>
#include <math.h>

// ---------------- problem constants ----------------
#define TSZ    480000
#define BATCH  8
#define CHUNK  4096
#define STRIDE 3072
#define NCH    157
#define NF     13
#define NFFT   1024
#define HOP    256
#define FBINS  513
#define HDIM   256
#define EDIM   128
#define N3H    768
#define SEQ    (BATCH*NCH)   // 1256
#define ROWS   (SEQ*NF)      // 16328
#define CPB    (NCH*NF)      // 2041
#define KPAD   528
#define PWLD   1152
#define NGB    1026
#define NTILE  79            // GRU seq tiles of 16
#define PI_F   3.14159265358979323846f

// ---------------- scratch ----------------
__device__ __nv_bfloat16 g_magh[ROWS*KPAD], g_magl[ROWS*KPAD];
__device__ float g_cosp[ROWS*FBINS];
__device__ float g_sinp[ROWS*FBINS];
__device__ float g_xg  [ROWS*N3H];
__device__ __nv_bfloat16 g_hsh[ROWS*HDIM], g_hsl[ROWS*HDIM];
__device__ float g_gb  [ROWS*NGB];
__device__ float g_y   [ROWS*NFFT];
__device__ float g_embrow[BATCH*N3H];
__device__ float g_wsum[CHUNK];
__device__ __nv_bfloat16 g_wxh[N3H*KPAD], g_wxl[N3H*KPAD];   // [n][k]
__device__ __nv_bfloat16 g_pwh[PWLD*HDIM], g_pwl[PWLD*HDIM]; // [n][k]
// GRU weights pre-padded in smem tile format: [g(4)][kc(8)][plane(2)][kg(2)][192][12] uints
#define GW_CH 9216
__device__ unsigned g_wpad[4*8*GW_CH];
// GRU h in padded ping-pong tile format: [parity(2)][tile(79)][kc(8)][plane(2)][kg(2)][16][12]
#define GA_CH 768
__device__ unsigned g_hpad[2*NTILE*8*GA_CH];
__device__ float g_twr[512], g_twi[512];
__device__ float g_win[NFFT];

__device__ __forceinline__ float sigf_fast(float x) { return 1.f/(1.f + __expf(-x)); }
__device__ __forceinline__ float tanh_fast(float x) { return 2.f/(1.f + __expf(-2.f*x)) - 1.f; }

__device__ __forceinline__ void bsplit(float v, __nv_bfloat16& h, __nv_bfloat16& l) {
    h = __float2bfloat16(v);
    l = __float2bfloat16(v - __bfloat162float(h));
}

__device__ __forceinline__ void mmab(float* c, const unsigned* a, unsigned b0, unsigned b1) {
    asm volatile("mma.sync.aligned.m16n8k16.row.col.f32.bf16.bf16.f32 "
        "{%0,%1,%2,%3}, {%4,%5,%6,%7}, {%8,%9}, {%0,%1,%2,%3};"
        : "+f"(c[0]), "+f"(c[1]), "+f"(c[2]), "+f"(c[3])
        : "r"(a[0]), "r"(a[1]), "r"(a[2]), "r"(a[3]), "r"(b0), "r"(b1));
}
__device__ __forceinline__ void cpa16(unsigned d, const void* s, int sz) {
    asm volatile("cp.async.ca.shared.global [%0], [%1], 16, %2;" :: "r"(d), "l"(s), "r"(sz));
}
#define CPA_COMMIT() asm volatile("cp.async.commit_group;")
#define CPA_WAIT()   asm volatile("cp.async.wait_all;" ::: "memory")

__device__ __forceinline__ void cpbulk(unsigned dst, const void* src, unsigned bytes, unsigned mbar) {
    asm volatile("cp.async.bulk.shared::cta.global.mbarrier::complete_tx::bytes "
                 "[%0], [%1], %2, [%3];"
                 :: "r"(dst), "l"(src), "r"(bytes), "r"(mbar) : "memory");
}
__device__ __forceinline__ void mbar_wait(unsigned mbar, unsigned parity) {
    unsigned done = 0;
    while (!done) {
        asm volatile("{\n\t.reg .pred p;\n\t"
            "mbarrier.try_wait.parity.acquire.cta.shared::cta.b64 p, [%1], %2;\n\t"
            "selp.b32 %0, 1, 0, p;\n\t}"
            : "=r"(done) : "r"(mbar), "r"(parity) : "memory");
    }
}

// ---------------- merged prep ----------------
#define PB_TAB 16
#define PB_WX  1584   // N3H*KPAD/256
#define PB_PW  1152   // PWLD*HDIM/256
#define PB_WP  1152   // 4*8*GW_CH/256
__global__ void k_prep(const float* __restrict__ wx,
                       const float* __restrict__ pw,
                       const float* __restrict__ wh,
                       const float* __restrict__ emb_table,
                       const int*   __restrict__ effect_id) {
    __shared__ float se[EDIM];
    const int bx = blockIdx.x, tid = threadIdx.x;
    if (bx < PB_TAB) {
        int i = bx*256 + tid;
        if (i < 512) {
            float s, c; sincosf(-(2.f*PI_F/NFFT)*i, &s, &c);
            g_twr[i] = c; g_twi[i] = s;
        }
        if (i < NFFT)
            g_win[i] = 0.5f - 0.5f*cosf((2.f*PI_F/NFFT)*i);
        if (i < CHUNK) {
            float ws = 0.f;
            for (int fi = 0; fi < NF; fi++) {
                int d = i - fi*HOP;
                if (d >= 0 && d < NFFT) {
                    float w = 0.5f - 0.5f*cosf((2.f*PI_F/NFFT)*d);
                    ws += w*w;
                }
            }
            g_wsum[i] = ws;
        }
    } else if (bx < PB_TAB + PB_WX) {
        int i = (bx - PB_TAB)*256 + tid;
        int n = i / KPAD, k = i % KPAD;
        float v = (k < FBINS) ? wx[(size_t)k*N3H + n] : 0.f;
        bsplit(v, g_wxh[i], g_wxl[i]);
    } else if (bx < PB_TAB + PB_WX + PB_PW) {
        int j = (bx - PB_TAB - PB_WX)*256 + tid;
        int n = j / HDIM, k = j % HDIM;
        float v = (n < NGB) ? pw[(size_t)k*NGB + n] : 0.f;
        bsplit(v, g_pwh[j], g_pwl[j]);
    } else if (bx < PB_TAB + PB_WX + PB_PW + PB_WP) {
        int j = (bx - PB_TAB - PB_WX - PB_PW)*256 + tid;   // 0..294911
        int g = j / 73728;
        int r1 = j % 73728;
        int kc = r1 / GW_CH;
        int r2 = r1 % GW_CH;
        int plane = r2 / 4608;
        int r3 = r2 % 4608;
        int kg = r3 / 2304;
        int r4 = r3 % 2304;
        int br = r4 / 12;
        int u  = r4 % 12;
        unsigned val = 0;
        if (u < 8) {
            int k = kc*32 + kg*16 + u*2;
            int n = ((br >> 6) << 8) + g*64 + (br & 63);
            float v0 = wh[(size_t)k*N3H + n];
            float v1 = wh[(size_t)(k+1)*N3H + n];
            __nv_bfloat16 h0, l0, h1, l1;
            bsplit(v0, h0, l0); bsplit(v1, h1, l1);
            unsigned lo16, hi16;
            if (plane == 0) { lo16 = __bfloat16_as_ushort(h0); hi16 = __bfloat16_as_ushort(h1); }
            else            { lo16 = __bfloat16_as_ushort(l0); hi16 = __bfloat16_as_ushort(l1); }
            val = (hi16 << 16) | lo16;
        }
        g_wpad[j] = val;
    } else {
        int b = bx - PB_TAB - PB_WX - PB_PW - PB_WP;   // 0..7
        if (tid < EDIM) se[tid] = emb_table[effect_id[b]*EDIM + tid];
        __syncthreads();
        for (int j = tid; j < N3H; j += 256) {
            float acc = 0.f;
            #pragma unroll 8
            for (int k = 0; k < EDIM; k++)
                acc += se[k] * wx[(size_t)(FBINS + k)*N3H + j];
            g_embrow[b*N3H + j] = acc;
        }
    }
}

// ---------------- forward STFT: 2 real frames per complex FFT, radix-4 core ----------------
__global__ void k_fwdfft(const float* __restrict__ audio) {
    __shared__ float sr[NFFT], si[NFFT];
    __shared__ float twr[512], twi[512];
    const int pr  = blockIdx.x;
    const int tid = threadIdx.x;
    const int fr0 = 2*pr, fr1 = fr0 + 1;
    const int b0 = fr0 / CPB, r0 = fr0 % CPB;
    const int b1 = fr1 / CPB, r1 = fr1 % CPB;
    const int base0 = (r0/NF)*STRIDE + (r0%NF)*HOP;
    const int base1 = (r1/NF)*STRIDE + (r1%NF)*HOP;

    for (int k = tid; k < 512; k += 256) { twr[k] = g_twr[k]; twi[k] = g_twi[k]; }
    for (int n = tid; n < NFFT; n += 256) {
        int s0 = base0 + n, s1 = base1 + n;
        float v0 = (s0 < TSZ) ? audio[b0*TSZ + s0] : 0.f;
        float v1 = (s1 < TSZ) ? audio[b1*TSZ + s1] : 0.f;
        float w = g_win[n];
        int j = __brev((unsigned)n) >> 22;
        sr[j] = v0*w; si[j] = v1*w;
    }
    __syncthreads();
    #pragma unroll
    for (int s = 1; s <= 9; s += 2) {
        const int h = 1 << (s-1);
        const int pos = tid & (h-1);
        const int grl = tid >> (s-1);
        const int base = (grl << (s+1)) + pos;
        const float wr1 = twr[pos << (10-s)], wi1 = twi[pos << (10-s)];
        const float wr2 = twr[pos << (9-s)],  wi2 = twi[pos << (9-s)];
        const int e3 = (pos + h) << (9-s);
        const float wr3 = twr[e3], wi3 = twi[e3];
        float x0r = sr[base],       x0i = si[base];
        float x1r = sr[base+h],     x1i = si[base+h];
        float x2r = sr[base+2*h],   x2i = si[base+2*h];
        float x3r = sr[base+3*h],   x3i = si[base+3*h];
        float t1r = wr1*x1r - wi1*x1i, t1i = wr1*x1i + wi1*x1r;
        float u0r = x0r + t1r, u0i = x0i + t1i;
        float u1r = x0r - t1r, u1i = x0i - t1i;
        float t3r = wr1*x3r - wi1*x3i, t3i = wr1*x3i + wi1*x3r;
        float u2r = x2r + t3r, u2i = x2i + t3i;
        float u3r = x2r - t3r, u3i = x2i - t3i;
        float v2r = wr2*u2r - wi2*u2i, v2i = wr2*u2i + wi2*u2r;
        float v3r = wr3*u3r - wi3*u3i, v3i = wr3*u3i + wi3*u3r;
        sr[base]       = u0r + v2r; si[base]       = u0i + v2i;
        sr[base+2*h]   = u0r - v2r; si[base+2*h]   = u0i - v2i;
        sr[base+h]     = u1r + v3r; si[base+h]     = u1i + v3i;
        sr[base+3*h]   = u1r - v3r; si[base+3*h]   = u1i - v3i;
        __syncthreads();
    }
    for (int k = tid; k < KPAD; k += 256) {
        if (k < FBINS) {
            int m = (NFFT - k) & (NFFT-1);
            float rek = sr[k], imk = si[k];
            float rem = sr[m], imm = si[m];
            float re0 = 0.5f*(rek + rem), i0 = 0.5f*(imk - imm);
            float re1 = 0.5f*(imk + imm), i1 = 0.5f*(rem - rek);
            float mag0 = sqrtf(re0*re0 + i0*i0);
            float c0, s0;
            if (mag0 > 1e-30f) { float inv = 1.f/mag0; c0 = re0*inv; s0 = i0*inv; }
            else               { c0 = 1.f; s0 = 0.f; }
            float mag1 = sqrtf(re1*re1 + i1*i1);
            float c1, s1;
            if (mag1 > 1e-30f) { float inv = 1.f/mag1; c1 = re1*inv; s1 = i1*inv; }
            else               { c1 = 1.f; s1 = 0.f; }
            bsplit(mag0, g_magh[fr0*KPAD + k], g_magl[fr0*KPAD + k]);
            bsplit(mag1, g_magh[fr1*KPAD + k], g_magl[fr1*KPAD + k]);
            g_cosp[fr0*FBINS + k] = c0; g_sinp[fr0*FBINS + k] = s0;
            g_cosp[fr1*FBINS + k] = c1; g_sinp[fr1*FBINS + k] = s1;
        } else {
            __nv_bfloat16 z = __float2bfloat16(0.f);
            g_magh[fr0*KPAD + k] = z; g_magl[fr0*KPAD + k] = z;
            g_magh[fr1*KPAD + k] = z; g_magl[fr1*KPAD + k] = z;
        }
    }
}

// ================= bf16-split 3-pass tensor GEMM (validated) =================
#define SM_PLANE (128*12)
#define SM_AH(p,r,c) smem_u[((p)*128 + (r))*12 + (c)]
#define SM_AL(p,r,c) smem_u[SM_PLANE*2 + ((p)*128 + (r))*12 + (c)]
#define SM_BH(p,r,c) smem_u[SM_PLANE*4 + ((p)*128 + (r))*12 + (c)]
#define SM_BL(p,r,c) smem_u[SM_PLANE*6 + ((p)*128 + (r))*12 + (c)]
#define SMEM_GEMM_BYTES (SM_PLANE*8*4)   // 49152

template<int NIT, int KSTRIDE>
__device__ __forceinline__ void gemm_core(
    unsigned* smem_u,
    const __nv_bfloat16* Ah_g, const __nv_bfloat16* Al_g, int a_row_max,
    const __nv_bfloat16* Bh_g, const __nv_bfloat16* Bl_g,
    int m0, int n0, float acc[2][8][4])
{
    const int tid = threadIdx.x;
    const int lane = tid & 31, wid = tid >> 5;
    const int wm = wid >> 1, wn = wid & 1;
    const int grp = lane >> 2, tig = lane & 3;
    const int row = tid >> 1, half = tid & 1;
    const int arow = m0 + row;
    const int asz = (arow < a_row_max) ? 16 : 0;
    const int brow = n0 + row;

    unsigned sbase = (unsigned)__cvta_generic_to_shared(smem_u);
    unsigned off = (row*12 + half*4)*4;
    unsigned dAh = sbase + off;
    unsigned dAl = sbase + SM_PLANE*2*4 + off;
    unsigned dBh = sbase + SM_PLANE*4*4 + off;
    unsigned dBl = sbase + SM_PLANE*6*4 + off;
    const unsigned bufB = 128*12*4;

    cpa16(dAh, Ah_g + (size_t)arow*KSTRIDE + half*8, asz);
    cpa16(dAl, Al_g + (size_t)arow*KSTRIDE + half*8, asz);
    cpa16(dBh, Bh_g + (size_t)brow*KSTRIDE + half*8, 16);
    cpa16(dBl, Bl_g + (size_t)brow*KSTRIDE + half*8, 16);
    CPA_COMMIT();
    CPA_WAIT();
    __syncthreads();

    #pragma unroll 1
    for (int it = 0; it < NIT; it++) {
        int p = it & 1, q = p ^ 1;
        if (it + 1 < NIT) {
            int k0 = (it+1)*16;
            cpa16(dAh + q*bufB, Ah_g + (size_t)arow*KSTRIDE + k0 + half*8, asz);
            cpa16(dAl + q*bufB, Al_g + (size_t)arow*KSTRIDE + k0 + half*8, asz);
            cpa16(dBh + q*bufB, Bh_g + (size_t)brow*KSTRIDE + k0 + half*8, 16);
            cpa16(dBl + q*bufB, Bl_g + (size_t)brow*KSTRIDE + k0 + half*8, 16);
            CPA_COMMIT();
        }
        unsigned afh[2][4], afl[2][4];
        #pragma unroll
        for (int mt = 0; mt < 2; mt++) {
            int rA = wm*32 + mt*16 + grp;
            afh[mt][0] = SM_AH(p, rA,   tig);
            afh[mt][1] = SM_AH(p, rA+8, tig);
            afh[mt][2] = SM_AH(p, rA,   tig+4);
            afh[mt][3] = SM_AH(p, rA+8, tig+4);
            afl[mt][0] = SM_AL(p, rA,   tig);
            afl[mt][1] = SM_AL(p, rA+8, tig);
            afl[mt][2] = SM_AL(p, rA,   tig+4);
            afl[mt][3] = SM_AL(p, rA+8, tig+4);
        }
        #pragma unroll
        for (int nt = 0; nt < 8; nt++) {
            int cB = wn*64 + nt*8 + grp;
            unsigned bh0 = SM_BH(p, cB, tig);
            unsigned bh1 = SM_BH(p, cB, tig+4);
            unsigned bl0 = SM_BL(p, cB, tig);
            unsigned bl1 = SM_BL(p, cB, tig+4);
            #pragma unroll
            for (int mt = 0; mt < 2; mt++) {
                mmab(acc[mt][nt], afh[mt], bh0, bh1);
                mmab(acc[mt][nt], afh[mt], bl0, bl1);
                mmab(acc[mt][nt], afl[mt], bh0, bh1);
            }
        }
        if (it + 1 < NIT) CPA_WAIT();
        __syncthreads();
    }
}

// ---- k_xg ----
__global__ __launch_bounds__(256, 2) void k_xg() {
    extern __shared__ unsigned smem_u[];
    const int tid = threadIdx.x;
    const int lane = tid & 31, wid = tid >> 5;
    const int wm = wid >> 1, wn = wid & 1;
    const int grp = lane >> 2, tig = lane & 3;
    const int m0 = blockIdx.y * 128, n0 = blockIdx.x * 128;
    float acc[2][8][4] = {};
    gemm_core<33, KPAD>(smem_u, g_magh, g_magl, ROWS, g_wxh, g_wxl, m0, n0, acc);
    #pragma unroll
    for (int mt = 0; mt < 2; mt++) {
        #pragma unroll
        for (int nt = 0; nt < 8; nt++) {
            int row0 = m0 + wm*32 + mt*16 + grp;
            int col0 = n0 + wn*64 + nt*8 + 2*tig;
            if (row0 < ROWS) {
                int b = row0 / CPB;
                g_xg[(size_t)row0*N3H + col0  ] = acc[mt][nt][0] + g_embrow[b*N3H + col0  ];
                g_xg[(size_t)row0*N3H + col0+1] = acc[mt][nt][1] + g_embrow[b*N3H + col0+1];
            }
            int row1 = row0 + 8;
            if (row1 < ROWS) {
                int b = row1 / CPB;
                g_xg[(size_t)row1*N3H + col0  ] = acc[mt][nt][2] + g_embrow[b*N3H + col0  ];
                g_xg[(size_t)row1*N3H + col0+1] = acc[mt][nt][3] + g_embrow[b*N3H + col0+1];
            }
        }
    }
}

// ---- k_proj ----
__global__ __launch_bounds__(256, 2) void k_proj(const float* __restrict__ pb) {
    extern __shared__ unsigned smem_u[];
    const int tid = threadIdx.x;
    const int lane = tid & 31, wid = tid >> 5;
    const int wm = wid >> 1, wn = wid & 1;
    const int grp = lane >> 2, tig = lane & 3;
    const int m0 = blockIdx.y * 128, n0 = blockIdx.x * 128;
    float acc[2][8][4] = {};
    gemm_core<16, HDIM>(smem_u, g_hsh, g_hsl, ROWS, g_pwh, g_pwl, m0, n0, acc);
    #pragma unroll
    for (int mt = 0; mt < 2; mt++) {
        #pragma unroll
        for (int nt = 0; nt < 8; nt++) {
            int row0 = m0 + wm*32 + mt*16 + grp;
            int col0 = n0 + wn*64 + nt*8 + 2*tig;
            if (row0 < ROWS) {
                if (col0   < NGB) g_gb[(size_t)row0*NGB + col0  ] = acc[mt][nt][0] + pb[col0  ];
                if (col0+1 < NGB) g_gb[(size_t)row0*NGB + col0+1] = acc[mt][nt][1] + pb[col0+1];
            }
            int row1 = row0 + 8;
            if (row1 < ROWS) {
                if (col0   < NGB) g_gb[(size_t)row1*NGB + col0  ] = acc[mt][nt][2] + pb[col0  ];
                if (col0+1 < NGB) g_gb[(size_t)row1*NGB + col0+1] = acc[mt][nt][3] + pb[col0+1];
            }
        }
    }
}

// ================= per-step GRU with cp.async.bulk (16 seqs x 192 cols, BK=32) =================
// grid (4, 79) = 316 blocks, 2 blocks/SM -> all SMs busy. smem (uints):
//   B [2buf][plane(2)][kg(2)][192][12] @0        (2*9216)
//   A [2buf][plane(2)][kg(2)][16][12]  @18432    (2*768)
//   mbar[2] @19968..19971. Total 19972 u -> 79888 bytes.
// hg staging floats [16][196] aliases B after final sync.
#define GB_BUF 9216
#define GB_A0  18432
#define GA_BUF 768
#define GMB    19968
#define GRUS_SMEM_BYTES 79888

__device__ __forceinline__ void gru_issue(unsigned sbase, int buf, int kc,
                                          int g, int tile, int t) {
    unsigned mbar = sbase + (GMB + buf)*4;
    unsigned bytes = (t > 0) ? (36864u + 3072u) : 36864u;
    asm volatile("mbarrier.arrive.expect_tx.shared.b64 _, [%0], %1;"
                 :: "r"(mbar), "r"(bytes) : "memory");
    cpbulk(sbase + (unsigned)(buf*GB_BUF)*4,
           g_wpad + ((size_t)g*8 + kc)*GW_CH, 36864u, mbar);
    if (t > 0)
        cpbulk(sbase + (unsigned)(GB_A0 + buf*GA_BUF)*4,
               g_hpad + (((size_t)((t-1)&1)*NTILE + tile)*8 + kc)*GA_CH, 3072u, mbar);
}

__global__ __launch_bounds__(256, 2) void k_gru(const float* __restrict__ gbias, int t) {
    extern __shared__ unsigned su[];
    const int tid = threadIdx.x;
    const int lane = tid & 31, wn = tid >> 5;   // 8 warps, each 24 cols (3 n8 tiles)
    const int grp = lane >> 2, tig = lane & 3;
    const int g = blockIdx.x, tile = blockIdx.y;
    const int sq0 = tile*16;
    unsigned sbase = (unsigned)__cvta_generic_to_shared(su);
    const unsigned mb0 = sbase + GMB*4, mb1 = sbase + (GMB+1)*4;
    // NOTE: mbar slots are 8 bytes; place them at distinct u64 slots
    // GMB*4 and (GMB+2)*4 to avoid overlap.
    const unsigned mbar0 = sbase + GMB*4;
    const unsigned mbar1 = sbase + (GMB+2)*4;
    (void)mb0; (void)mb1;

    if (tid == 0) {
        asm volatile("mbarrier.init.shared.b64 [%0], 1;" :: "r"(mbar0) : "memory");
        asm volatile("mbarrier.init.shared.b64 [%0], 1;" :: "r"(mbar1) : "memory");
    }
    if (t == 0)
        for (int i = tid; i < 2*GA_BUF; i += 256) su[GB_A0 + i] = 0;
    __syncthreads();
    if (tid == 0) {
        // re-derive issue with correct barrier addresses
        unsigned bytes = (t > 0) ? (36864u + 3072u) : 36864u;
        asm volatile("mbarrier.arrive.expect_tx.shared.b64 _, [%0], %1;" :: "r"(mbar0), "r"(bytes) : "memory");
        cpbulk(sbase, g_wpad + ((size_t)g*8 + 0)*GW_CH, 36864u, mbar0);
        if (t > 0) cpbulk(sbase + (unsigned)GB_A0*4,
                          g_hpad + (((size_t)((t-1)&1)*NTILE + tile)*8 + 0)*GA_CH, 3072u, mbar0);
        asm volatile("mbarrier.arrive.expect_tx.shared.b64 _, [%0], %1;" :: "r"(mbar1), "r"(bytes) : "memory");
        cpbulk(sbase + (unsigned)GB_BUF*4, g_wpad + ((size_t)g*8 + 1)*GW_CH, 36864u, mbar1);
        if (t > 0) cpbulk(sbase + (unsigned)(GB_A0 + GA_BUF)*4,
                          g_hpad + (((size_t)((t-1)&1)*NTILE + tile)*8 + 1)*GA_CH, 3072u, mbar1);
    }

    float acc[3][4] = {};
    #pragma unroll 1
    for (int kc = 0; kc < 8; kc++) {
        int b = kc & 1;
        mbar_wait(b ? mbar1 : mbar0, (kc >> 1) & 1);
        #pragma unroll
        for (int kg = 0; kg < 2; kg++) {
            int Ab = GB_A0 + b*GA_BUF + kg*192;
            unsigned afh[4], afl[4];
            afh[0] = su[Ab + grp*12 + tig];
            afh[1] = su[Ab + (grp+8)*12 + tig];
            afh[2] = su[Ab + grp*12 + tig+4];
            afh[3] = su[Ab + (grp+8)*12 + tig+4];
            afl[0] = su[Ab + 384 + grp*12 + tig];
            afl[1] = su[Ab + 384 + (grp+8)*12 + tig];
            afl[2] = su[Ab + 384 + grp*12 + tig+4];
            afl[3] = su[Ab + 384 + (grp+8)*12 + tig+4];
            #pragma unroll
            for (int nt = 0; nt < 3; nt++) {
                int Bb = b*GB_BUF + kg*2304 + (wn*24 + nt*8 + grp)*12;
                unsigned bh0 = su[Bb + tig];
                unsigned bh1 = su[Bb + tig+4];
                unsigned bl0 = su[Bb + 4608 + tig];
                unsigned bl1 = su[Bb + 4608 + tig+4];
                mmab(acc[nt], afh, bh0, bh1);
                mmab(acc[nt], afh, bl0, bl1);
                mmab(acc[nt], afl, bh0, bh1);
            }
        }
        __syncthreads();
        if (kc + 2 < 8 && tid == 0) {
            unsigned mbar = b ? mbar1 : mbar0;
            unsigned bytes = (t > 0) ? (36864u + 3072u) : 36864u;
            asm volatile("mbarrier.arrive.expect_tx.shared.b64 _, [%0], %1;" :: "r"(mbar), "r"(bytes) : "memory");
            cpbulk(sbase + (unsigned)(b*GB_BUF)*4,
                   g_wpad + ((size_t)g*8 + kc+2)*GW_CH, 36864u, mbar);
            if (t > 0) cpbulk(sbase + (unsigned)(GB_A0 + b*GA_BUF)*4,
                              g_hpad + (((size_t)((t-1)&1)*NTILE + tile)*8 + kc+2)*GA_CH, 3072u, mbar);
        }
    }
    // stage hg floats [16][196] over B region (all mma reads complete)
    float* hg = (float*)su;
    #pragma unroll
    for (int nt = 0; nt < 3; nt++) {
        int c0 = wn*24 + nt*8 + 2*tig;
        hg[grp*196 + c0]       = acc[nt][0];
        hg[grp*196 + c0+1]     = acc[nt][1];
        hg[(grp+8)*196 + c0]   = acc[nt][2];
        hg[(grp+8)*196 + c0+1] = acc[nt][3];
    }
    __syncthreads();
    // fused gates: 16 seqs x 64 hidden cols
    __nv_bfloat16* hpB = (__nv_bfloat16*)g_hpad;
    #pragma unroll
    for (int i = 0; i < 4; i++) {
        int e = tid + i*256;
        int s = e >> 6, cc = e & 63;
        int sq = sq0 + s;
        if (sq >= SEQ) continue;
        int c = g*64 + cc;
        const float* xg = g_xg + (size_t)(sq*NF + t)*N3H;
        float z = sigf_fast(xg[c]           + hg[s*196 + cc]        + gbias[c]);
        float r = sigf_fast(xg[HDIM + c]    + hg[s*196 + 64 + cc]   + gbias[HDIM + c]);
        float n = tanh_fast(xg[2*HDIM + c] + r*(hg[s*196 + 128 + cc] + gbias[2*HDIM + c]));
        float hp = 0.f;
        if (t > 0) {
            size_t pi = (size_t)(sq*NF + t - 1)*HDIM + c;
            hp = __bfloat162float(g_hsh[pi]) + __bfloat162float(g_hsl[pi]);
        }
        float h = (1.f - z)*n + z*hp;
        __nv_bfloat16 hh, hl;
        bsplit(h, hh, hl);
        size_t gi = (size_t)(sq*NF + t)*HDIM + c;
        g_hsh[gi] = hh; g_hsl[gi] = hl;
        // padded ping-pong write for next step's bulk load
        int kc2 = c >> 5, kg2 = (c >> 4) & 1, u2 = (c & 15) >> 1, hf = c & 1;
        size_t ub = (((size_t)(t&1)*NTILE + tile)*8 + kc2)*GA_CH + kg2*192 + s*12 + u2;
        hpB[ub*2 + hf]         = hh;
        hpB[(ub + 384)*2 + hf] = hl;
    }
}

// ---------------- modulate + inverse FFT (radix-4 core, 2 frames/block) ----------------
__global__ void k_modinv() {
    __shared__ float sre0[FBINS], sim0[FBINS], sre1[FBINS], sim1[FBINS];
    __shared__ float sr[NFFT], si[NFFT];
    __shared__ float twr[512], twi[512];
    const int pr  = blockIdx.x;
    const int tid = threadIdx.x;
    const int fr0 = 2*pr, fr1 = fr0 + 1;

    for (int k = tid; k < 512; k += 256) { twr[k] = g_twr[k]; twi[k] = g_twi[k]; }
    for (int k = tid; k < FBINS; k += 256) {
        float mag0 = __bfloat162float(g_magh[fr0*KPAD + k]) + __bfloat162float(g_magl[fr0*KPAD + k]);
        float mm0 = g_gb[(size_t)fr0*NGB + k]*mag0 + g_gb[(size_t)fr0*NGB + FBINS + k];
        sre0[k] = mm0 * g_cosp[fr0*FBINS + k];
        sim0[k] = mm0 * g_sinp[fr0*FBINS + k];
        float mag1 = __bfloat162float(g_magh[fr1*KPAD + k]) + __bfloat162float(g_magl[fr1*KPAD + k]);
        float mm1 = g_gb[(size_t)fr1*NGB + k]*mag1 + g_gb[(size_t)fr1*NGB + FBINS + k];
        sre1[k] = mm1 * g_cosp[fr1*FBINS + k];
        sim1[k] = mm1 * g_sinp[fr1*FBINS + k];
    }
    __syncthreads();
    for (int n = tid; n < NFFT; n += 256) {
        float zr, zi;
        if (n <= 512) { zr = sre0[n] - sim1[n];         zi = sim0[n] + sre1[n]; }
        else { int m = NFFT - n; zr = sre0[m] + sim1[m]; zi = sre1[m] - sim0[m]; }
        int j = __brev((unsigned)n) >> 22;
        sr[j] = zr; si[j] = zi;
    }
    __syncthreads();
    #pragma unroll
    for (int s = 1; s <= 9; s += 2) {
        const int h = 1 << (s-1);
        const int pos = tid & (h-1);
        const int grl = tid >> (s-1);
        const int base = (grl << (s+1)) + pos;
        const float wr1 = twr[pos << (10-s)], wi1 = -twi[pos << (10-s)];
        const float wr2 = twr[pos << (9-s)],  wi2 = -twi[pos << (9-s)];
        const int e3 = (pos + h) << (9-s);
        const float wr3 = twr[e3], wi3 = -twi[e3];
        float x0r = sr[base],       x0i = si[base];
        float x1r = sr[base+h],     x1i = si[base+h];
        float x2r = sr[base+2*h],   x2i = si[base+2*h];
        float x3r = sr[base+3*h],   x3i = si[base+3*h];
        float t1r = wr1*x1r - wi1*x1i, t1i = wr1*x1i + wi1*x1r;
        float u0r = x0r + t1r, u0i = x0i + t1i;
        float u1r = x0r - t1r, u1i = x0i - t1i;
        float t3r = wr1*x3r - wi1*x3i, t3i = wr1*x3i + wi1*x3r;
        float u2r = x2r + t3r, u2i = x2i + t3i;
        float u3r = x2r - t3r, u3i = x2i - t3i;
        float v2r = wr2*u2r - wi2*u2i, v2i = wr2*u2i + wi2*u2r;
        float v3r = wr3*u3r - wi3*u3i, v3i = wr3*u3i + wi3*u3r;
        sr[base]       = u0r + v2r; si[base]       = u0i + v2i;
        sr[base+2*h]   = u0r - v2r; si[base+2*h]   = u0i - v2i;
        sr[base+h]     = u1r + v3r; si[base+h]     = u1i + v3i;
        sr[base+3*h]   = u1r - v3r; si[base+3*h]   = u1i - v3i;
        __syncthreads();
    }
    const float invn = 1.f/(float)NFFT;
    for (int n = tid; n < NFFT; n += 256) {
        float w = invn*g_win[n];
        g_y[(size_t)fr0*NFFT + n] = sr[n]*w;
        g_y[(size_t)fr1*NFFT + n] = si[n]*w;
    }
}

// ---------------- overlap-add ----------------
__global__ void k_overlap(float* __restrict__ out) {
    const int t = blockIdx.x*blockDim.x + threadIdx.x;
    const int b = blockIdx.y;
    if (t >= TSZ) return;
    int ci_hi = t / STRIDE; if (ci_hi > NCH-1) ci_hi = NCH-1;
    int v = t - (CHUNK - 1);
    int ci_lo = (v <= 0) ? 0 : (v + STRIDE - 1)/STRIDE;
    float acc = 0.f;
    for (int ci = ci_lo; ci <= ci_hi; ci++) {
        int n = t - ci*STRIDE;
        int fi_hi = n >> 8; if (fi_hi > NF-1) fi_hi = NF-1;
        int w = n - (NFFT - 1);
        int fi_lo = (w <= 0) ? 0 : (w + HOP - 1) >> 8;
        float s = 0.f;
        for (int fi = fi_lo; fi <= fi_hi; fi++)
            s += g_y[(size_t)(((b*NCH + ci)*NF) + fi)*NFFT + n - fi*HOP];
        acc += s / fmaxf(g_wsum[n], 1e-8f);
    }
    out[b*TSZ + t] = acc;
}

// ---------------- launch ----------------
extern "C" void kernel_launch(void* const* d_in, const int* in_sizes, int n_in,
                              void* d_out, int out_size) {
    const float* audio     = (const float*)d_in[0];
    const float* emb_table = (const float*)d_in[1];
    const float* gru_wx    = (const float*)d_in[2];
    const float* gru_wh    = (const float*)d_in[3];
    const float* gru_b     = (const float*)d_in[4];
    const float* proj_w    = (const float*)d_in[5];
    const float* proj_b    = (const float*)d_in[6];
    const int*   effect_id = (const int*)  d_in[7];
    float* out = (float*)d_out;

    cudaFuncSetAttribute(k_gru, cudaFuncAttributeMaxDynamicSharedMemorySize,
                         GRUS_SMEM_BYTES + 16);   // + mbar slack; idempotent host-side call

    k_prep<<<PB_TAB + PB_WX + PB_PW + PB_WP + BATCH, 256>>>(
        gru_wx, proj_w, gru_wh, emb_table, effect_id);                        // 1
    k_fwdfft<<<ROWS/2, 256>>>(audio);                                         // 2
    k_xg<<<dim3(N3H/128, (ROWS + 127)/128), 256, SMEM_GEMM_BYTES>>>();        // 3
    for (int t = 0; t < NF; t++)                                              // 4.. (slot 4 = t=0)
        k_gru<<<dim3(4, NTILE), 256, GRUS_SMEM_BYTES + 16>>>(gru_b, t);
    k_proj<<<dim3(PWLD/128, (ROWS + 127)/128), 256, SMEM_GEMM_BYTES>>>(proj_b);
    k_modinv<<<ROWS/2, 256>>>();
    k_overlap<<<dim3((TSZ + 255)/256, BATCH), 256>>>(out);
}

// round 14
// speedup vs baseline: 1.3406x; 1.0731x over previous
#include <cuda_runtime.h>
#include <cuda_bf16.h>
#include <math.h>

// ---------------- problem constants ----------------
#define TSZ    480000
#define BATCH  8
#define CHUNK  4096
#define STRIDE 3072
#define NCH    157
#define NF     13
#define NFFT   1024
#define HOP    256
#define FBINS  513
#define HDIM   256
#define EDIM   128
#define N3H    768
#define SEQ    (BATCH*NCH)   // 1256
#define ROWS   (SEQ*NF)      // 16328
#define CPB    (NCH*NF)      // 2041
#define NGB    1026
#define NTILE  79            // GRU seq tiles of 16
#define MT     128           // row tiles of 128 (16384 rows)
#define NKX    17            // xg K-chunks (544)
#define NKP    8             // proj K-chunks (256)
#define CH_U   6144          // uints per (tile,chunk) operand block: [plane2][kg2][128][12]
#define PI_F   3.14159265358979323846f

// ---------------- scratch ----------------
__device__ float g_cosp[ROWS*FBINS];
__device__ float g_sinp[ROWS*FBINS];
__device__ float g_xg  [ROWS*N3H];
__device__ float g_gb  [ROWS*NGB];
__device__ float g_y   [ROWS*NFFT];
__device__ float g_embrow[BATCH*N3H];
__device__ float g_wsum[CHUNK];
// chunked operand storage (zero at module load; pad regions never written or rewritten each call)
__device__ unsigned g_xpad [MT*NKX*CH_U];    // mag A     (53.5 MB)
__device__ unsigned g_wxpad[6*NKX*CH_U];     // wx B
__device__ unsigned g_hspad[MT*NKP*CH_U];    // h A for proj (25 MB)
__device__ unsigned g_pwpad[9*NKP*CH_U];     // pw B
// GRU weights: [g(4)][kc(8)][plane(2)][kg(2)][192][12] uints
#define GW_CH 9216
__device__ unsigned g_wpad[4*8*GW_CH];
// GRU h ping-pong: [parity(2)][tile(79)][kc(8)][plane(2)][kg(2)][16][12]
#define GA_CH 768
__device__ unsigned g_hpad[2*NTILE*8*GA_CH];
__device__ float g_twr[512], g_twi[512];
__device__ float g_win[NFFT];

__device__ __forceinline__ float sigf_fast(float x) { return 1.f/(1.f + __expf(-x)); }
__device__ __forceinline__ float tanh_fast(float x) { return 2.f/(1.f + __expf(-2.f*x)) - 1.f; }

__device__ __forceinline__ void bsplit(float v, __nv_bfloat16& h, __nv_bfloat16& l) {
    h = __float2bfloat16(v);
    l = __float2bfloat16(v - __bfloat162float(h));
}

__device__ __forceinline__ void mmab(float* c, const unsigned* a, unsigned b0, unsigned b1) {
    asm volatile("mma.sync.aligned.m16n8k16.row.col.f32.bf16.bf16.f32 "
        "{%0,%1,%2,%3}, {%4,%5,%6,%7}, {%8,%9}, {%0,%1,%2,%3};"
        : "+f"(c[0]), "+f"(c[1]), "+f"(c[2]), "+f"(c[3])
        : "r"(a[0]), "r"(a[1]), "r"(a[2]), "r"(a[3]), "r"(b0), "r"(b1));
}
__device__ __forceinline__ void cpbulk(unsigned dst, const void* src, unsigned bytes, unsigned mbar) {
    asm volatile("cp.async.bulk.shared::cta.global.mbarrier::complete_tx::bytes "
                 "[%0], [%1], %2, [%3];"
                 :: "r"(dst), "l"(src), "r"(bytes), "r"(mbar) : "memory");
}
__device__ __forceinline__ void mbar_init1(unsigned mbar) {
    asm volatile("mbarrier.init.shared.b64 [%0], 1;" :: "r"(mbar) : "memory");
}
__device__ __forceinline__ void mbar_expect(unsigned mbar, unsigned bytes) {
    asm volatile("mbarrier.arrive.expect_tx.shared.b64 _, [%0], %1;"
                 :: "r"(mbar), "r"(bytes) : "memory");
}
__device__ __forceinline__ void mbar_wait(unsigned mbar, unsigned parity) {
    unsigned done = 0;
    while (!done) {
        asm volatile("{\n\t.reg .pred p;\n\t"
            "mbarrier.try_wait.parity.acquire.cta.shared::cta.b64 p, [%1], %2;\n\t"
            "selp.b32 %0, 1, 0, p;\n\t}"
            : "=r"(done) : "r"(mbar), "r"(parity) : "memory");
    }
}

// pack two bf16-split values into a uint for plane (0=hi,1=lo)
__device__ __forceinline__ unsigned packplane(float v0, float v1, int plane) {
    __nv_bfloat16 h0, l0, h1, l1;
    bsplit(v0, h0, l0); bsplit(v1, h1, l1);
    unsigned lo16 = plane ? __bfloat16_as_ushort(l0) : __bfloat16_as_ushort(h0);
    unsigned hi16 = plane ? __bfloat16_as_ushort(l1) : __bfloat16_as_ushort(h1);
    return (hi16 << 16) | lo16;
}

// ---------------- merged prep ----------------
#define PB_TAB 16
#define PB_WX2 2448   // 6*NKX*CH_U/256
#define PB_PW2 1728   // 9*NKP*CH_U/256
#define PB_WP  1152   // 4*8*GW_CH/256
__global__ void k_prep(const float* __restrict__ wx,
                       const float* __restrict__ pw,
                       const float* __restrict__ wh,
                       const float* __restrict__ emb_table,
                       const int*   __restrict__ effect_id) {
    __shared__ float se[EDIM];
    const int bx = blockIdx.x, tid = threadIdx.x;
    if (bx < PB_TAB) {
        int i = bx*256 + tid;
        if (i < 512) {
            float s, c; sincosf(-(2.f*PI_F/NFFT)*i, &s, &c);
            g_twr[i] = c; g_twi[i] = s;
        }
        if (i < NFFT)
            g_win[i] = 0.5f - 0.5f*cosf((2.f*PI_F/NFFT)*i);
        if (i < CHUNK) {
            float ws = 0.f;
            for (int fi = 0; fi < NF; fi++) {
                int d = i - fi*HOP;
                if (d >= 0 && d < NFFT) {
                    float w = 0.5f - 0.5f*cosf((2.f*PI_F/NFFT)*d);
                    ws += w*w;
                }
            }
            g_wsum[i] = ws;
        }
    } else if (bx < PB_TAB + PB_WX2) {
        int j = (bx - PB_TAB)*256 + tid;               // 0..626687
        int tk = j / CH_U, rem = j % CH_U;
        int ntile = tk / NKX, kc = tk % NKX;
        int plane = rem / 3072; int r2 = rem % 3072;
        int kg = r2 / 1536;     int r3 = r2 % 1536;
        int rr = r3 / 12;       int u  = r3 % 12;
        unsigned val = 0;
        if (u < 8) {
            int k0 = kc*32 + kg*16 + u*2;
            int n = ntile*128 + rr;
            float v0 = (k0   < FBINS) ? wx[(size_t)k0*N3H + n] : 0.f;
            float v1 = (k0+1 < FBINS) ? wx[(size_t)(k0+1)*N3H + n] : 0.f;
            val = packplane(v0, v1, plane);
        }
        g_wxpad[j] = val;
    } else if (bx < PB_TAB + PB_WX2 + PB_PW2) {
        int j = (bx - PB_TAB - PB_WX2)*256 + tid;      // 0..442367
        int tk = j / CH_U, rem = j % CH_U;
        int ntile = tk / NKP, kc = tk % NKP;
        int plane = rem / 3072; int r2 = rem % 3072;
        int kg = r2 / 1536;     int r3 = r2 % 1536;
        int rr = r3 / 12;       int u  = r3 % 12;
        unsigned val = 0;
        int n = ntile*128 + rr;
        if (u < 8 && n < NGB) {
            int k0 = kc*32 + kg*16 + u*2;
            float v0 = pw[(size_t)k0*NGB + n];
            float v1 = pw[(size_t)(k0+1)*NGB + n];
            val = packplane(v0, v1, plane);
        }
        g_pwpad[j] = val;
    } else if (bx < PB_TAB + PB_WX2 + PB_PW2 + PB_WP) {
        int j = (bx - PB_TAB - PB_WX2 - PB_PW2)*256 + tid;
        int g = j / 73728;
        int r1 = j % 73728;
        int kc = r1 / GW_CH;
        int r2 = r1 % GW_CH;
        int plane = r2 / 4608;
        int r3 = r2 % 4608;
        int kg = r3 / 2304;
        int r4 = r3 % 2304;
        int br = r4 / 12;
        int u  = r4 % 12;
        unsigned val = 0;
        if (u < 8) {
            int k = kc*32 + kg*16 + u*2;
            int n = ((br >> 6) << 8) + g*64 + (br & 63);
            val = packplane(wh[(size_t)k*N3H + n], wh[(size_t)(k+1)*N3H + n], plane);
        }
        g_wpad[j] = val;
    } else {
        int b = bx - PB_TAB - PB_WX2 - PB_PW2 - PB_WP;   // 0..7
        if (tid < EDIM) se[tid] = emb_table[effect_id[b]*EDIM + tid];
        __syncthreads();
        for (int j = tid; j < N3H; j += 256) {
            float acc = 0.f;
            #pragma unroll 8
            for (int k = 0; k < EDIM; k++)
                acc += se[k] * wx[(size_t)(FBINS + k)*N3H + j];
            g_embrow[b*N3H + j] = acc;
        }
    }
}

// ---------------- forward STFT: 2 real frames per complex FFT, radix-4 core ----------------
__global__ void k_fwdfft(const float* __restrict__ audio) {
    __shared__ float sr[NFFT], si[NFFT];
    __shared__ float twr[512], twi[512];
    const int pr  = blockIdx.x;
    const int tid = threadIdx.x;
    const int fr0 = 2*pr, fr1 = fr0 + 1;
    const int b0 = fr0 / CPB, r0 = fr0 % CPB;
    const int b1 = fr1 / CPB, r1 = fr1 % CPB;
    const int base0 = (r0/NF)*STRIDE + (r0%NF)*HOP;
    const int base1 = (r1/NF)*STRIDE + (r1%NF)*HOP;

    for (int k = tid; k < 512; k += 256) { twr[k] = g_twr[k]; twi[k] = g_twi[k]; }
    for (int n = tid; n < NFFT; n += 256) {
        int s0 = base0 + n, s1 = base1 + n;
        float v0 = (s0 < TSZ) ? audio[b0*TSZ + s0] : 0.f;
        float v1 = (s1 < TSZ) ? audio[b1*TSZ + s1] : 0.f;
        float w = g_win[n];
        int j = __brev((unsigned)n) >> 22;
        sr[j] = v0*w; si[j] = v1*w;
    }
    __syncthreads();
    #pragma unroll
    for (int s = 1; s <= 9; s += 2) {
        const int h = 1 << (s-1);
        const int pos = tid & (h-1);
        const int grl = tid >> (s-1);
        const int base = (grl << (s+1)) + pos;
        const float wr1 = twr[pos << (10-s)], wi1 = twi[pos << (10-s)];
        const float wr2 = twr[pos << (9-s)],  wi2 = twi[pos << (9-s)];
        const int e3 = (pos + h) << (9-s);
        const float wr3 = twr[e3], wi3 = twi[e3];
        float x0r = sr[base],       x0i = si[base];
        float x1r = sr[base+h],     x1i = si[base+h];
        float x2r = sr[base+2*h],   x2i = si[base+2*h];
        float x3r = sr[base+3*h],   x3i = si[base+3*h];
        float t1r = wr1*x1r - wi1*x1i, t1i = wr1*x1i + wi1*x1r;
        float u0r = x0r + t1r, u0i = x0i + t1i;
        float u1r = x0r - t1r, u1i = x0i - t1i;
        float t3r = wr1*x3r - wi1*x3i, t3i = wr1*x3i + wi1*x3r;
        float u2r = x2r + t3r, u2i = x2i + t3i;
        float u3r = x2r - t3r, u3i = x2i - t3i;
        float v2r = wr2*u2r - wi2*u2i, v2i = wr2*u2i + wi2*u2r;
        float v3r = wr3*u3r - wi3*u3i, v3i = wr3*u3i + wi3*u3r;
        sr[base]       = u0r + v2r; si[base]       = u0i + v2i;
        sr[base+2*h]   = u0r - v2r; si[base+2*h]   = u0i - v2i;
        sr[base+h]     = u1r + v3r; si[base+h]     = u1i + v3i;
        sr[base+3*h]   = u1r - v3r; si[base+3*h]   = u1i - v3i;
        __syncthreads();
    }
    __nv_bfloat16* xp = (__nv_bfloat16*)g_xpad;
    for (int k = tid; k < NKX*32; k += 256) {
        float mag0 = 0.f, mag1 = 0.f;
        if (k < FBINS) {
            int m = (NFFT - k) & (NFFT-1);
            float rek = sr[k], imk = si[k];
            float rem = sr[m], imm = si[m];
            float re0 = 0.5f*(rek + rem), i0 = 0.5f*(imk - imm);
            float re1 = 0.5f*(imk + imm), i1 = 0.5f*(rem - rek);
            mag0 = sqrtf(re0*re0 + i0*i0);
            float c0, s0;
            if (mag0 > 1e-30f) { float inv = 1.f/mag0; c0 = re0*inv; s0 = i0*inv; }
            else               { c0 = 1.f; s0 = 0.f; }
            mag1 = sqrtf(re1*re1 + i1*i1);
            float c1, s1;
            if (mag1 > 1e-30f) { float inv = 1.f/mag1; c1 = re1*inv; s1 = i1*inv; }
            else               { c1 = 1.f; s1 = 0.f; }
            g_cosp[fr0*FBINS + k] = c0; g_sinp[fr0*FBINS + k] = s0;
            g_cosp[fr1*FBINS + k] = c1; g_sinp[fr1*FBINS + k] = s1;
        }
        int kc = k >> 5, kg = (k >> 4) & 1, u = (k & 15) >> 1, hf = k & 1;
        __nv_bfloat16 hh, hl;
        size_t p0 = ((size_t)(fr0 >> 7)*NKX + kc)*CH_U + kg*1536 + (fr0 & 127)*12 + u;
        bsplit(mag0, hh, hl);
        xp[p0*2 + hf] = hh; xp[(p0 + 3072)*2 + hf] = hl;
        size_t p1 = ((size_t)(fr1 >> 7)*NKX + kc)*CH_U + kg*1536 + (fr1 & 127)*12 + u;
        bsplit(mag1, hh, hl);
        xp[p1*2 + hf] = hh; xp[(p1 + 3072)*2 + hf] = hl;
    }
}

// ================= bulk-load bf16-split tensor GEMM =================
// block: 128m x 128n, 8 warps (4x2). smem: 2 x 12288 uints (A 6144 | B 6144) + 2 mbars.
#define GX_BUF 12288
#define GX_MBU 24576
#define GXS_BYTES (24580*4)   // 98320

template<int NKC>
__device__ __forceinline__ void gemm_bulk(unsigned* su, const unsigned* Ag, const unsigned* Bg,
                                          int mtile, int ntile, float acc[2][8][4]) {
    const int tid = threadIdx.x;
    const int lane = tid & 31, wid = tid >> 5;
    const int wm = wid >> 1, wn = wid & 1;
    const int grp = lane >> 2, tig = lane & 3;
    unsigned sbase = (unsigned)__cvta_generic_to_shared(su);
    const unsigned mbar0 = sbase + GX_MBU*4, mbar1 = sbase + (GX_MBU+2)*4;

    if (tid == 0) { mbar_init1(mbar0); mbar_init1(mbar1); }
    __syncthreads();
    if (tid == 0) {
        mbar_expect(mbar0, 49152u);
        cpbulk(sbase,                 Ag + ((size_t)mtile*NKC + 0)*CH_U, 24576u, mbar0);
        cpbulk(sbase + 6144u*4,       Bg + ((size_t)ntile*NKC + 0)*CH_U, 24576u, mbar0);
        mbar_expect(mbar1, 49152u);
        cpbulk(sbase + GX_BUF*4u,     Ag + ((size_t)mtile*NKC + 1)*CH_U, 24576u, mbar1);
        cpbulk(sbase + (GX_BUF+6144u)*4, Bg + ((size_t)ntile*NKC + 1)*CH_U, 24576u, mbar1);
    }
    #pragma unroll 1
    for (int kc = 0; kc < NKC; kc++) {
        int b = kc & 1;
        mbar_wait(b ? mbar1 : mbar0, (kc >> 1) & 1);
        #pragma unroll
        for (int kg = 0; kg < 2; kg++) {
            int A0 = b*GX_BUF + kg*1536;
            unsigned afh[2][4], afl[2][4];
            #pragma unroll
            for (int mt = 0; mt < 2; mt++) {
                int rA = wm*32 + mt*16 + grp;
                afh[mt][0] = su[A0 + rA*12 + tig];
                afh[mt][1] = su[A0 + (rA+8)*12 + tig];
                afh[mt][2] = su[A0 + rA*12 + tig+4];
                afh[mt][3] = su[A0 + (rA+8)*12 + tig+4];
                afl[mt][0] = su[A0 + 3072 + rA*12 + tig];
                afl[mt][1] = su[A0 + 3072 + (rA+8)*12 + tig];
                afl[mt][2] = su[A0 + 3072 + rA*12 + tig+4];
                afl[mt][3] = su[A0 + 3072 + (rA+8)*12 + tig+4];
            }
            #pragma unroll
            for (int nt = 0; nt < 8; nt++) {
                int cB = wn*64 + nt*8 + grp;
                int B0 = b*GX_BUF + 6144 + kg*1536 + cB*12;
                unsigned bh0 = su[B0 + tig];
                unsigned bh1 = su[B0 + tig+4];
                unsigned bl0 = su[B0 + 3072 + tig];
                unsigned bl1 = su[B0 + 3072 + tig+4];
                #pragma unroll
                for (int mt = 0; mt < 2; mt++) {
                    mmab(acc[mt][nt], afh[mt], bh0, bh1);
                    mmab(acc[mt][nt], afh[mt], bl0, bl1);
                    mmab(acc[mt][nt], afl[mt], bh0, bh1);
                }
            }
        }
        __syncthreads();
        if (kc + 2 < NKC && tid == 0) {
            unsigned mbar = b ? mbar1 : mbar0;
            mbar_expect(mbar, 49152u);
            cpbulk(sbase + (unsigned)(b*GX_BUF)*4,
                   Ag + ((size_t)mtile*NKC + kc+2)*CH_U, 24576u, mbar);
            cpbulk(sbase + (unsigned)(b*GX_BUF + 6144)*4,
                   Bg + ((size_t)ntile*NKC + kc+2)*CH_U, 24576u, mbar);
        }
    }
}

// ---- k_xg ----
__global__ __launch_bounds__(256, 2) void k_xg() {
    extern __shared__ unsigned smem_u[];
    const int tid = threadIdx.x;
    const int lane = tid & 31, wid = tid >> 5;
    const int wm = wid >> 1, wn = wid & 1;
    const int grp = lane >> 2, tig = lane & 3;
    const int mtile = blockIdx.y, ntile = blockIdx.x;
    const int m0 = mtile*128, n0 = ntile*128;
    float acc[2][8][4] = {};
    gemm_bulk<NKX>(smem_u, g_xpad, g_wxpad, mtile, ntile, acc);
    #pragma unroll
    for (int mt = 0; mt < 2; mt++) {
        #pragma unroll
        for (int nt = 0; nt < 8; nt++) {
            int row0 = m0 + wm*32 + mt*16 + grp;
            int col0 = n0 + wn*64 + nt*8 + 2*tig;
            if (row0 < ROWS) {
                int b = row0 / CPB;
                g_xg[(size_t)row0*N3H + col0  ] = acc[mt][nt][0] + g_embrow[b*N3H + col0  ];
                g_xg[(size_t)row0*N3H + col0+1] = acc[mt][nt][1] + g_embrow[b*N3H + col0+1];
            }
            int row1 = row0 + 8;
            if (row1 < ROWS) {
                int b = row1 / CPB;
                g_xg[(size_t)row1*N3H + col0  ] = acc[mt][nt][2] + g_embrow[b*N3H + col0  ];
                g_xg[(size_t)row1*N3H + col0+1] = acc[mt][nt][3] + g_embrow[b*N3H + col0+1];
            }
        }
    }
}

// ---- k_proj ----
__global__ __launch_bounds__(256, 2) void k_proj(const float* __restrict__ pb) {
    extern __shared__ unsigned smem_u[];
    const int tid = threadIdx.x;
    const int lane = tid & 31, wid = tid >> 5;
    const int wm = wid >> 1, wn = wid & 1;
    const int grp = lane >> 2, tig = lane & 3;
    const int mtile = blockIdx.y, ntile = blockIdx.x;
    const int m0 = mtile*128, n0 = ntile*128;
    float acc[2][8][4] = {};
    gemm_bulk<NKP>(smem_u, g_hspad, g_pwpad, mtile, ntile, acc);
    #pragma unroll
    for (int mt = 0; mt < 2; mt++) {
        #pragma unroll
        for (int nt = 0; nt < 8; nt++) {
            int row0 = m0 + wm*32 + mt*16 + grp;
            int col0 = n0 + wn*64 + nt*8 + 2*tig;
            if (row0 < ROWS) {
                if (col0   < NGB) g_gb[(size_t)row0*NGB + col0  ] = acc[mt][nt][0] + pb[col0  ];
                if (col0+1 < NGB) g_gb[(size_t)row0*NGB + col0+1] = acc[mt][nt][1] + pb[col0+1];
            }
            int row1 = row0 + 8;
            if (row1 < ROWS) {
                if (col0   < NGB) g_gb[(size_t)row1*NGB + col0  ] = acc[mt][nt][2] + pb[col0  ];
                if (col0+1 < NGB) g_gb[(size_t)row1*NGB + col0+1] = acc[mt][nt][3] + pb[col0+1];
            }
        }
    }
}

// ================= per-step GRU with cp.async.bulk (16 seqs x 192 cols, BK=32) =================
#define GB_BUF 9216
#define GB_A0  18432
#define GA_BUF 768
#define GMB    19968
#define GRUS_SMEM_BYTES (19972*4 + 16)

__global__ __launch_bounds__(256, 2) void k_gru(const float* __restrict__ gbias, int t) {
    extern __shared__ unsigned su[];
    const int tid = threadIdx.x;
    const int lane = tid & 31, wn = tid >> 5;
    const int grp = lane >> 2, tig = lane & 3;
    const int g = blockIdx.x, tile = blockIdx.y;
    const int sq0 = tile*16;
    unsigned sbase = (unsigned)__cvta_generic_to_shared(su);
    const unsigned mbar0 = sbase + GMB*4;
    const unsigned mbar1 = sbase + (GMB+2)*4;

    if (tid == 0) { mbar_init1(mbar0); mbar_init1(mbar1); }
    if (t == 0)
        for (int i = tid; i < 2*GA_BUF; i += 256) su[GB_A0 + i] = 0;
    __syncthreads();
    if (tid == 0) {
        unsigned bytes = (t > 0) ? (36864u + 3072u) : 36864u;
        mbar_expect(mbar0, bytes);
        cpbulk(sbase, g_wpad + ((size_t)g*8 + 0)*GW_CH, 36864u, mbar0);
        if (t > 0) cpbulk(sbase + (unsigned)GB_A0*4,
                          g_hpad + (((size_t)((t-1)&1)*NTILE + tile)*8 + 0)*GA_CH, 3072u, mbar0);
        mbar_expect(mbar1, bytes);
        cpbulk(sbase + (unsigned)GB_BUF*4, g_wpad + ((size_t)g*8 + 1)*GW_CH, 36864u, mbar1);
        if (t > 0) cpbulk(sbase + (unsigned)(GB_A0 + GA_BUF)*4,
                          g_hpad + (((size_t)((t-1)&1)*NTILE + tile)*8 + 1)*GA_CH, 3072u, mbar1);
    }

    float acc[3][4] = {};
    #pragma unroll 1
    for (int kc = 0; kc < 8; kc++) {
        int b = kc & 1;
        mbar_wait(b ? mbar1 : mbar0, (kc >> 1) & 1);
        #pragma unroll
        for (int kg = 0; kg < 2; kg++) {
            int Ab = GB_A0 + b*GA_BUF + kg*192;
            unsigned afh[4], afl[4];
            afh[0] = su[Ab + grp*12 + tig];
            afh[1] = su[Ab + (grp+8)*12 + tig];
            afh[2] = su[Ab + grp*12 + tig+4];
            afh[3] = su[Ab + (grp+8)*12 + tig+4];
            afl[0] = su[Ab + 384 + grp*12 + tig];
            afl[1] = su[Ab + 384 + (grp+8)*12 + tig];
            afl[2] = su[Ab + 384 + grp*12 + tig+4];
            afl[3] = su[Ab + 384 + (grp+8)*12 + tig+4];
            #pragma unroll
            for (int nt = 0; nt < 3; nt++) {
                int Bb = b*GB_BUF + kg*2304 + (wn*24 + nt*8 + grp)*12;
                unsigned bh0 = su[Bb + tig];
                unsigned bh1 = su[Bb + tig+4];
                unsigned bl0 = su[Bb + 4608 + tig];
                unsigned bl1 = su[Bb + 4608 + tig+4];
                mmab(acc[nt], afh, bh0, bh1);
                mmab(acc[nt], afh, bl0, bl1);
                mmab(acc[nt], afl, bh0, bh1);
            }
        }
        __syncthreads();
        if (kc + 2 < 8 && tid == 0) {
            unsigned mbar = b ? mbar1 : mbar0;
            unsigned bytes = (t > 0) ? (36864u + 3072u) : 36864u;
            mbar_expect(mbar, bytes);
            cpbulk(sbase + (unsigned)(b*GB_BUF)*4,
                   g_wpad + ((size_t)g*8 + kc+2)*GW_CH, 36864u, mbar);
            if (t > 0) cpbulk(sbase + (unsigned)(GB_A0 + b*GA_BUF)*4,
                              g_hpad + (((size_t)((t-1)&1)*NTILE + tile)*8 + kc+2)*GA_CH, 3072u, mbar);
        }
    }
    float* hg = (float*)su;
    #pragma unroll
    for (int nt = 0; nt < 3; nt++) {
        int c0 = wn*24 + nt*8 + 2*tig;
        hg[grp*196 + c0]       = acc[nt][0];
        hg[grp*196 + c0+1]     = acc[nt][1];
        hg[(grp+8)*196 + c0]   = acc[nt][2];
        hg[(grp+8)*196 + c0+1] = acc[nt][3];
    }
    __syncthreads();
    __nv_bfloat16* hpB = (__nv_bfloat16*)g_hpad;
    __nv_bfloat16* hsp = (__nv_bfloat16*)g_hspad;
    #pragma unroll
    for (int i = 0; i < 4; i++) {
        int e = tid + i*256;
        int s = e >> 6, cc = e & 63;
        int sq = sq0 + s;
        if (sq >= SEQ) continue;
        int c = g*64 + cc;
        int hf = c & 1;
        const float* xg = g_xg + (size_t)(sq*NF + t)*N3H;
        float z = sigf_fast(xg[c]           + hg[s*196 + cc]        + gbias[c]);
        float r = sigf_fast(xg[HDIM + c]    + hg[s*196 + 64 + cc]   + gbias[HDIM + c]);
        float n = tanh_fast(xg[2*HDIM + c] + r*(hg[s*196 + 128 + cc] + gbias[2*HDIM + c]));
        float hp = 0.f;
        if (t > 0) {
            int prow = sq*NF + t - 1;
            size_t pbs = ((size_t)(prow>>7)*NKP + (c>>5))*CH_U + ((c>>4)&1)*1536
                         + (prow&127)*12 + ((c&15)>>1);
            hp = __bfloat162float(hsp[pbs*2 + hf]) + __bfloat162float(hsp[(pbs+3072)*2 + hf]);
        }
        float h = (1.f - z)*n + z*hp;
        __nv_bfloat16 hh, hl;
        bsplit(h, hh, hl);
        int row = sq*NF + t;
        size_t wbs = ((size_t)(row>>7)*NKP + (c>>5))*CH_U + ((c>>4)&1)*1536
                     + (row&127)*12 + ((c&15)>>1);
        hsp[wbs*2 + hf] = hh; hsp[(wbs+3072)*2 + hf] = hl;
        int kc2 = c >> 5, kg2 = (c >> 4) & 1, u2 = (c & 15) >> 1;
        size_t ub = (((size_t)(t&1)*NTILE + tile)*8 + kc2)*GA_CH + kg2*192 + s*12 + u2;
        hpB[ub*2 + hf]         = hh;
        hpB[(ub + 384)*2 + hf] = hl;
    }
}

// ---------------- modulate + inverse FFT (radix-4 core, 2 frames/block) ----------------
__global__ void k_modinv() {
    __shared__ float sre0[FBINS], sim0[FBINS], sre1[FBINS], sim1[FBINS];
    __shared__ float sr[NFFT], si[NFFT];
    __shared__ float twr[512], twi[512];
    const int pr  = blockIdx.x;
    const int tid = threadIdx.x;
    const int fr0 = 2*pr, fr1 = fr0 + 1;
    const __nv_bfloat16* xp = (const __nv_bfloat16*)g_xpad;

    for (int k = tid; k < 512; k += 256) { twr[k] = g_twr[k]; twi[k] = g_twi[k]; }
    for (int k = tid; k < FBINS; k += 256) {
        int kc = k >> 5, kg = (k >> 4) & 1, u = (k & 15) >> 1, hf = k & 1;
        size_t p0 = ((size_t)(fr0>>7)*NKX + kc)*CH_U + kg*1536 + (fr0&127)*12 + u;
        float mag0 = __bfloat162float(xp[p0*2 + hf]) + __bfloat162float(xp[(p0+3072)*2 + hf]);
        float mm0 = g_gb[(size_t)fr0*NGB + k]*mag0 + g_gb[(size_t)fr0*NGB + FBINS + k];
        sre0[k] = mm0 * g_cosp[fr0*FBINS + k];
        sim0[k] = mm0 * g_sinp[fr0*FBINS + k];
        size_t p1 = ((size_t)(fr1>>7)*NKX + kc)*CH_U + kg*1536 + (fr1&127)*12 + u;
        float mag1 = __bfloat162float(xp[p1*2 + hf]) + __bfloat162float(xp[(p1+3072)*2 + hf]);
        float mm1 = g_gb[(size_t)fr1*NGB + k]*mag1 + g_gb[(size_t)fr1*NGB + FBINS + k];
        sre1[k] = mm1 * g_cosp[fr1*FBINS + k];
        sim1[k] = mm1 * g_sinp[fr1*FBINS + k];
    }
    __syncthreads();
    for (int n = tid; n < NFFT; n += 256) {
        float zr, zi;
        if (n <= 512) { zr = sre0[n] - sim1[n];         zi = sim0[n] + sre1[n]; }
        else { int m = NFFT - n; zr = sre0[m] + sim1[m]; zi = sre1[m] - sim0[m]; }
        int j = __brev((unsigned)n) >> 22;
        sr[j] = zr; si[j] = zi;
    }
    __syncthreads();
    #pragma unroll
    for (int s = 1; s <= 9; s += 2) {
        const int h = 1 << (s-1);
        const int pos = tid & (h-1);
        const int grl = tid >> (s-1);
        const int base = (grl << (s+1)) + pos;
        const float wr1 = twr[pos << (10-s)], wi1 = -twi[pos << (10-s)];
        const float wr2 = twr[pos << (9-s)],  wi2 = -twi[pos << (9-s)];
        const int e3 = (pos + h) << (9-s);
        const float wr3 = twr[e3], wi3 = -twi[e3];
        float x0r = sr[base],       x0i = si[base];
        float x1r = sr[base+h],     x1i = si[base+h];
        float x2r = sr[base+2*h],   x2i = si[base+2*h];
        float x3r = sr[base+3*h],   x3i = si[base+3*h];
        float t1r = wr1*x1r - wi1*x1i, t1i = wr1*x1i + wi1*x1r;
        float u0r = x0r + t1r, u0i = x0i + t1i;
        float u1r = x0r - t1r, u1i = x0i - t1i;
        float t3r = wr1*x3r - wi1*x3i, t3i = wr1*x3i + wi1*x3r;
        float u2r = x2r + t3r, u2i = x2i + t3i;
        float u3r = x2r - t3r, u3i = x2i - t3i;
        float v2r = wr2*u2r - wi2*u2i, v2i = wr2*u2i + wi2*u2r;
        float v3r = wr3*u3r - wi3*u3i, v3i = wr3*u3i + wi3*u3r;
        sr[base]       = u0r + v2r; si[base]       = u0i + v2i;
        sr[base+2*h]   = u0r - v2r; si[base+2*h]   = u0i - v2i;
        sr[base+h]     = u1r + v3r; si[base+h]     = u1i + v3i;
        sr[base+3*h]   = u1r - v3r; si[base+3*h]   = u1i - v3i;
        __syncthreads();
    }
    const float invn = 1.f/(float)NFFT;
    for (int n = tid; n < NFFT; n += 256) {
        float w = invn*g_win[n];
        g_y[(size_t)fr0*NFFT + n] = sr[n]*w;
        g_y[(size_t)fr1*NFFT + n] = si[n]*w;
    }
}

// ---------------- overlap-add ----------------
__global__ void k_overlap(float* __restrict__ out) {
    const int t = blockIdx.x*blockDim.x + threadIdx.x;
    const int b = blockIdx.y;
    if (t >= TSZ) return;
    int ci_hi = t / STRIDE; if (ci_hi > NCH-1) ci_hi = NCH-1;
    int v = t - (CHUNK - 1);
    int ci_lo = (v <= 0) ? 0 : (v + STRIDE - 1)/STRIDE;
    float acc = 0.f;
    for (int ci = ci_lo; ci <= ci_hi; ci++) {
        int n = t - ci*STRIDE;
        int fi_hi = n >> 8; if (fi_hi > NF-1) fi_hi = NF-1;
        int w = n - (NFFT - 1);
        int fi_lo = (w <= 0) ? 0 : (w + HOP - 1) >> 8;
        float s = 0.f;
        for (int fi = fi_lo; fi <= fi_hi; fi++)
            s += g_y[(size_t)(((b*NCH + ci)*NF) + fi)*NFFT + n - fi*HOP];
        acc += s / fmaxf(g_wsum[n], 1e-8f);
    }
    out[b*TSZ + t] = acc;
}

// ---------------- launch ----------------
extern "C" void kernel_launch(void* const* d_in, const int* in_sizes, int n_in,
                              void* d_out, int out_size) {
    const float* audio     = (const float*)d_in[0];
    const float* emb_table = (const float*)d_in[1];
    const float* gru_wx    = (const float*)d_in[2];
    const float* gru_wh    = (const float*)d_in[3];
    const float* gru_b     = (const float*)d_in[4];
    const float* proj_w    = (const float*)d_in[5];
    const float* proj_b    = (const float*)d_in[6];
    const int*   effect_id = (const int*)  d_in[7];
    float* out = (float*)d_out;

    cudaFuncSetAttribute(k_gru,  cudaFuncAttributeMaxDynamicSharedMemorySize, GRUS_SMEM_BYTES);
    cudaFuncSetAttribute(k_xg,   cudaFuncAttributeMaxDynamicSharedMemorySize, GXS_BYTES);
    cudaFuncSetAttribute(k_proj, cudaFuncAttributeMaxDynamicSharedMemorySize, GXS_BYTES);

    k_prep<<<PB_TAB + PB_WX2 + PB_PW2 + PB_WP + BATCH, 256>>>(
        gru_wx, proj_w, gru_wh, emb_table, effect_id);                        // 1
    k_fwdfft<<<ROWS/2, 256>>>(audio);                                         // 2
    k_xg<<<dim3(6, MT), 256, GXS_BYTES>>>();                                  // 3
    for (int t = 0; t < NF; t++)                                              // 4.. (slot 4 = t=0)
        k_gru<<<dim3(4, NTILE), 256, GRUS_SMEM_BYTES>>>(gru_b, t);
    k_proj<<<dim3(9, MT), 256, GXS_BYTES>>>(proj_b);
    k_modinv<<<ROWS/2, 256>>>();
    k_overlap<<<dim3((TSZ + 255)/256, BATCH), 256>>>(out);
}